// round 14
// baseline (speedup 1.0000x reference)
#include <cuda_runtime.h>
#include <cuda_bf16.h>
#include <cstdint>

#define B_ 64
#define T_ 1024
#define I_ 256
#define H_ 512
#define O_ 256
#define G_ 1536   // 3*H

// ======================= scratch (device globals) =======================
__device__ float g_gates[(size_t)T_ * G_ * B_];   // [t][g][b]
__device__ float g_out0[(size_t)T_ * H_ * B_];    // [t][h][b]
__device__ float g_out1[(size_t)T_ * H_ * B_];    // [t][h][b]
__device__ unsigned g_cnt[8 * 32];                 // per-group barrier counters (padded)
__device__ unsigned g_gen2[8 * 32];                // per-group generations (padded)
__device__ unsigned short g_hbh[2 * 64 * 512];     // h bf16-hi, parity double buffer, [b][k]
__device__ unsigned short g_hbl[2 * 64 * 512];     // h bf16-lo

// pre-swizzled bf16 operand tiles (GEMM phase)
__device__ __nv_bfloat16 g_w0h[12 * 4 * 8192], g_w0l[12 * 4 * 8192];
__device__ __nv_bfloat16 g_w1h[12 * 8 * 8192], g_w1l[12 * 8 * 8192];
__device__ __nv_bfloat16 g_wfh[ 2 * 8 * 8192], g_wfl[ 2 * 8 * 8192];
__device__ __nv_bfloat16 g_x0h[(size_t)T_ * 4 * 4096], g_x0l[(size_t)T_ * 4 * 4096];
__device__ __nv_bfloat16 g_x1h[(size_t)T_ * 8 * 4096], g_x1l[(size_t)T_ * 8 * 4096];

// ======================= small helpers =======================
__device__ __forceinline__ void cp_async16(void* smem_dst, const void* gsrc) {
    unsigned s = (unsigned)__cvta_generic_to_shared(smem_dst);
    asm volatile("cp.async.ca.shared.global [%0], [%1], 16;" :: "r"(s), "l"(gsrc));
}
__device__ __forceinline__ void cp_commit() {
    asm volatile("cp.async.commit_group;");
}
template <int N>
__device__ __forceinline__ void cp_wait() {
    asm volatile("cp.async.wait_group %0;" :: "n"(N));
}
__device__ __forceinline__ unsigned atom_add_release(unsigned* p, unsigned v) {
    unsigned old;
    asm volatile("atom.add.release.gpu.global.u32 %0, [%1], %2;"
                 : "=r"(old) : "l"(p), "r"(v) : "memory");
    return old;
}
__device__ __forceinline__ unsigned ld_acquire(const unsigned* p) {
    unsigned v;
    asm volatile("ld.acquire.gpu.global.u32 %0, [%1];" : "=r"(v) : "l"(p) : "memory");
    return v;
}
__device__ __forceinline__ void st_release(unsigned* p, unsigned v) {
    asm volatile("st.release.gpu.global.u32 [%0], %1;" :: "l"(p), "r"(v) : "memory");
}
__device__ __forceinline__ uint32_t smem_u32(const void* p) {
    return (uint32_t)__cvta_generic_to_shared(p);
}
__host__ __device__ __forceinline__ uint32_t swz128(uint32_t o) {
    return o ^ ((o >> 3) & 0x70);
}
__device__ __forceinline__ unsigned short bf16hi_bits(float v, float& rem) {
    __nv_bfloat16 b = __float2bfloat16(v);
    rem = v - __bfloat162float(b);
    return *reinterpret_cast<unsigned short*>(&b);
}
__device__ __forceinline__ unsigned short bf16_bits(float v) {
    __nv_bfloat16 b = __float2bfloat16(v);
    return *reinterpret_cast<unsigned short*>(&b);
}

// ---- mma.sync / ldmatrix (base-target PTX) ----
__device__ __forceinline__ void ldsm_x4(unsigned* r, uint32_t addr) {
    asm volatile("ldmatrix.sync.aligned.m8n8.x4.shared.b16 {%0,%1,%2,%3}, [%4];"
        : "=r"(r[0]), "=r"(r[1]), "=r"(r[2]), "=r"(r[3]) : "r"(addr));
}
__device__ __forceinline__ void mma_bf16(float* d, const unsigned* a, const unsigned* b) {
    asm volatile(
        "mma.sync.aligned.m16n8k16.row.col.f32.bf16.bf16.f32 "
        "{%0,%1,%2,%3}, {%4,%5,%6,%7}, {%8,%9}, {%0,%1,%2,%3};"
        : "+f"(d[0]), "+f"(d[1]), "+f"(d[2]), "+f"(d[3])
        : "r"(a[0]), "r"(a[1]), "r"(a[2]), "r"(a[3]), "r"(b[0]), "r"(b[1]));
}

// =========================================================================
// Prep: W [M,K] fp32 -> hi/lo bf16 SW128 tiles [mi][s][128x64]
// =========================================================================
__global__ __launch_bounds__(256) void k_prep_w(
    const float* __restrict__ src, __nv_bfloat16* __restrict__ dh,
    __nv_bfloat16* __restrict__ dl, int K)
{
    int mi = blockIdx.x, s = blockIdx.y, nS = gridDim.y;
    size_t tbase = ((size_t)mi * nS + s) * 16384;
#pragma unroll
    for (int i = 0; i < 8; i++) {
        int it  = threadIdx.x + i * 256;
        int row = it >> 4;
        int q   = it & 15;
        float4 v = *(const float4*)(src + (size_t)(mi * 128 + row) * K + s * 64 + q * 4);
        float r0, r1, r2, r3;
        ushort4 hi, lo;
        hi.x = bf16hi_bits(v.x, r0); hi.y = bf16hi_bits(v.y, r1);
        hi.z = bf16hi_bits(v.z, r2); hi.w = bf16hi_bits(v.w, r3);
        lo.x = bf16_bits(r0); lo.y = bf16_bits(r1);
        lo.z = bf16_bits(r2); lo.w = bf16_bits(r3);
        uint32_t sw = swz128((uint32_t)(row * 128 + q * 8));
        *(ushort4*)((char*)dh + tbase + sw) = hi;
        *(ushort4*)((char*)dl + tbase + sw) = lo;
    }
}

// =========================================================================
// Prep: x[b][t][k] fp32 -> hi/lo bf16 SW128 tiles [t][s][64(b)x64(k)]
// =========================================================================
__global__ __launch_bounds__(256) void k_prep_x(const float* __restrict__ x) {
    int t = blockIdx.x, s = blockIdx.y, nS = gridDim.y;
    size_t tbase = ((size_t)t * nS + s) * 8192;
#pragma unroll
    for (int i = 0; i < 4; i++) {
        int it = threadIdx.x + i * 256;
        int b  = it >> 4;
        int q  = it & 15;
        float4 v = *(const float4*)(x + ((size_t)b * T_ + t) * I_ + s * 64 + q * 4);
        float r0, r1, r2, r3;
        ushort4 hi, lo;
        hi.x = bf16hi_bits(v.x, r0); hi.y = bf16hi_bits(v.y, r1);
        hi.z = bf16hi_bits(v.z, r2); hi.w = bf16hi_bits(v.w, r3);
        lo.x = bf16_bits(r0); lo.y = bf16_bits(r1);
        lo.z = bf16_bits(r2); lo.w = bf16_bits(r3);
        uint32_t sw = swz128((uint32_t)(b * 128 + q * 8));
        *(ushort4*)((char*)g_x0h + tbase + sw) = hi;
        *(ushort4*)((char*)g_x0l + tbase + sw) = lo;
    }
}

// =========================================================================
// Prep: out[t][h][b] fp32 -> hi/lo bf16 SW128 tiles [t][s][64(b)x64(k)]
// =========================================================================
__global__ __launch_bounds__(256) void k_prep_h(
    const float* __restrict__ src, __nv_bfloat16* __restrict__ dh,
    __nv_bfloat16* __restrict__ dl)
{
    __shared__ float sm[64 * 65];
    int t = blockIdx.x, s = blockIdx.y, nS = gridDim.y;
    size_t tbase = ((size_t)t * nS + s) * 8192;
    const float* blk = src + ((size_t)t * H_ + s * 64) * B_;
#pragma unroll
    for (int i = 0; i < 16; i++) {
        int idx = threadIdx.x + i * 256;
        int k = idx >> 6, b = idx & 63;
        sm[k * 65 + b] = blk[idx];
    }
    __syncthreads();
#pragma unroll
    for (int i = 0; i < 4; i++) {
        int it = threadIdx.x + i * 256;
        int b  = it >> 4;
        int q  = it & 15;
        float v0 = sm[(q * 4 + 0) * 65 + b];
        float v1 = sm[(q * 4 + 1) * 65 + b];
        float v2 = sm[(q * 4 + 2) * 65 + b];
        float v3 = sm[(q * 4 + 3) * 65 + b];
        float r0, r1, r2, r3;
        ushort4 hi, lo;
        hi.x = bf16hi_bits(v0, r0); hi.y = bf16hi_bits(v1, r1);
        hi.z = bf16hi_bits(v2, r2); hi.w = bf16hi_bits(v3, r3);
        lo.x = bf16_bits(r0); lo.y = bf16_bits(r1);
        lo.z = bf16_bits(r2); lo.w = bf16_bits(r3);
        uint32_t sw = swz128((uint32_t)(b * 128 + q * 8));
        *(ushort4*)((char*)dh + tbase + sw) = hi;
        *(ushort4*)((char*)dl + tbase + sw) = lo;
    }
}

// =========================================================================
// mma.sync GEMM (R10 proven version: M=128 tiles)
// =========================================================================
#define TCB_BYTES 65536
#define TC_SMEM_TOTAL (1024 + 2 * TCB_BYTES)

__device__ __forceinline__ void ldsm_x2(unsigned* r, uint32_t addr) {
    asm volatile("ldmatrix.sync.aligned.m8n8.x2.shared.b16 {%0,%1}, [%2];"
        : "=r"(r[0]), "=r"(r[1]) : "r"(addr));
}

__global__ __launch_bounds__(256) void k_gemm_mma(
    const __nv_bfloat16* __restrict__ Wh, const __nv_bfloat16* __restrict__ Wl,
    const __nv_bfloat16* __restrict__ Xh, const __nv_bfloat16* __restrict__ Xl,
    const float* __restrict__ bias, float* __restrict__ C,
    int nS, int M, int mode)
{
    extern __shared__ __align__(16) char smem[];
    uint32_t sb = smem_u32(smem);
    int tid  = threadIdx.x;
    int wid  = tid >> 5;
    int lane = tid & 31;
    int mi   = blockIdx.x;
    int m0   = mi * 128;
    int t0   = blockIdx.y * 2;

    int wm = (wid >> 1) * 32;
    int wn = (wid & 1);

    uint32_t pA = (uint32_t)((wm + (lane & 15)) * 128 + (lane >> 4) * 16);
    uint32_t rowB = (uint32_t)((lane & 7) + ((lane >> 4) & 1) * 8);
    uint32_t koffB = (uint32_t)(((lane >> 3) & 1) * 16);

    float acc[2][8][4];
#pragma unroll
    for (int i = 0; i < 2; i++)
#pragma unroll
        for (int n = 0; n < 8; n++)
#pragma unroll
            for (int c = 0; c < 4; c++) acc[i][n][c] = 0.f;

    auto issue_slab = [&](int s, int bi) {
        char* dst = smem + 1024 + bi * TCB_BYTES;
        const char* wh  = (const char*)Wh + ((size_t)mi * nS + s) * 16384;
        const char* wl  = (const char*)Wl + ((size_t)mi * nS + s) * 16384;
        const char* x0h = (const char*)Xh + ((size_t)t0 * nS + s) * 8192;
        const char* x1h = (const char*)Xh + ((size_t)(t0 + 1) * nS + s) * 8192;
        const char* x0l = (const char*)Xl + ((size_t)t0 * nS + s) * 8192;
        const char* x1l = (const char*)Xl + ((size_t)(t0 + 1) * nS + s) * 8192;
#pragma unroll
        for (int i = 0; i < 16; i++) {
            int c   = tid + i * 256;
            int reg = c >> 10;
            int off = (c & 1023) * 16;
            const char* src;
            if      (reg == 0) src = wh + off;
            else if (reg == 1) src = wl + off;
            else if (reg == 2) src = (off < 8192) ? x0h + off : x1h + (off - 8192);
            else               src = (off < 8192) ? x0l + off : x1l + (off - 8192);
            cp_async16(dst + reg * 16384 + off, src);
        }
        cp_commit();
    };

    issue_slab(0, 0);

    for (int s = 0; s < nS; s++) {
        int bi = s & 1;
        if (s + 1 < nS) {
            issue_slab(s + 1, (s + 1) & 1);
            cp_wait<1>();
        } else {
            cp_wait<0>();
        }
        __syncthreads();

        uint32_t bufb = sb + 1024 + (uint32_t)bi * TCB_BYTES;
        uint32_t aH = bufb;
        uint32_t aL = bufb + 16384;
        uint32_t bH = bufb + 32768 + (uint32_t)wn * 8192;
        uint32_t bL = bufb + 49152 + (uint32_t)wn * 8192;

#pragma unroll
        for (int ks = 0; ks < 4; ks++) {
            unsigned ah[2][4], al[2][4];
            ldsm_x4(ah[0], aH + swz128(pA + ks * 32));
            ldsm_x4(ah[1], aH + swz128(pA + 2048 + ks * 32));
            ldsm_x4(al[0], aL + swz128(pA + ks * 32));
            ldsm_x4(al[1], aL + swz128(pA + 2048 + ks * 32));
#pragma unroll
            for (int half = 0; half < 2; half++) {
                unsigned bh2[2][4], bl2[2][4];
#pragma unroll
                for (int np2 = 0; np2 < 2; np2++) {
                    int np = half * 2 + np2;
                    uint32_t pB = (uint32_t)((np * 16 + rowB) * 128) + koffB;
                    ldsm_x4(bh2[np2], bH + swz128(pB + ks * 32));
                    ldsm_x4(bl2[np2], bL + swz128(pB + ks * 32));
                }
#pragma unroll
                for (int np2 = 0; np2 < 2; np2++) {
#pragma unroll
                    for (int e = 0; e < 2; e++) {
                        int nt = half * 4 + np2 * 2 + e;
                        const unsigned* bfh = &bh2[np2][e * 2];
                        const unsigned* bfl = &bl2[np2][e * 2];
#pragma unroll
                        for (int i = 0; i < 2; i++) {
                            mma_bf16(acc[i][nt], ah[i], bfh);
                            mma_bf16(acc[i][nt], ah[i], bfl);
                            mma_bf16(acc[i][nt], al[i], bfh);
                        }
                    }
                }
            }
        }
        __syncthreads();
    }

    int qrow = lane >> 2;
    int qcol = (lane & 3) * 2;

    if (mode == 0) {
        int t = t0 + wn;
#pragma unroll
        for (int i = 0; i < 2; i++) {
            int r0 = wm + i * 16 + qrow;
            int r1 = r0 + 8;
            float bb0 = bias[m0 + r0];
            float bb1 = bias[m0 + r1];
            float* d0 = C + ((size_t)t * M + m0 + r0) * B_;
            float* d1 = C + ((size_t)t * M + m0 + r1) * B_;
#pragma unroll
            for (int nt = 0; nt < 8; nt++) {
                int col = nt * 8 + qcol;
                *(float2*)(d0 + col) = make_float2(acc[i][nt][0] + bb0, acc[i][nt][1] + bb0);
                *(float2*)(d1 + col) = make_float2(acc[i][nt][2] + bb1, acc[i][nt][3] + bb1);
            }
        }
    } else {
        float* stage = (float*)(smem + 1024);
#pragma unroll
        for (int i = 0; i < 2; i++) {
            int r0 = wm + i * 16 + qrow;
            int r1 = r0 + 8;
            float bb0 = bias[m0 + r0];
            float bb1 = bias[m0 + r1];
#pragma unroll
            for (int nt = 0; nt < 8; nt++) {
                int col = wn * 64 + nt * 8 + qcol;
                stage[r0 * 132 + col]     = acc[i][nt][0] + bb0;
                stage[r0 * 132 + col + 1] = acc[i][nt][1] + bb0;
                stage[r1 * 132 + col]     = acc[i][nt][2] + bb1;
                stage[r1 * 132 + col + 1] = acc[i][nt][3] + bb1;
            }
        }
        __syncthreads();
        int n    = tid >> 1;
        int half = tid & 1;
        int tt   = t0 + (n >> 6);
        int b2   = n & 63;
        float* dst = C + ((size_t)b2 * T_ + tt) * M + m0 + half * 64;
#pragma unroll
        for (int q = 0; q < 16; q++) {
            float4 v = make_float4(stage[(half * 64 + q * 4 + 0) * 132 + n],
                                   stage[(half * 64 + q * 4 + 1) * 132 + n],
                                   stage[(half * 64 + q * 4 + 2) * 132 + n],
                                   stage[(half * 64 + q * 4 + 3) * 132 + n]);
            *(float4*)(dst + q * 4) = v;
        }
    }
}

// =========================================================================
// Persistent GRU layer: W fragments REGISTER-RESIDENT (smem-read once),
// 16-batch groups.
// 128 CTAs = 4 groups (16 b) x 32 j-subs (16 j = 48 gate rows).
// 6 MMA warps: 3 m16-tiles x 2 K-halves; A regs = 16 chunks x4 x{hi,lo}.
// Per-step smem reads: only h (B operand) + hg/stage.
// =========================================================================
#define OFF_WL  49920
#define OFF_HH  99840
#define OFF_HL  116480
#define OFF_HG  133120
#define HG_STRIDE 18
#define HG_HALF (48 * HG_STRIDE * 4)          // 3456 bytes
#define OFF_STG (OFF_HG + 2 * HG_HALF)        // 140032
#define GRU11_SMEM_BYTES (OFF_STG + 1024)     // 141056

__global__ __launch_bounds__(256) void k_gru11(
    const float* __restrict__ gates,   // [t][g][b], includes b_ih
    const float* __restrict__ Whh,     // [3H][H]
    const float* __restrict__ bhh,     // [3H]
    float* __restrict__ out,           // [t][h][b]
    unsigned short* __restrict__ hbh,  // [2][64][512] bf16-hi bits
    unsigned short* __restrict__ hbl)  // [2][64][512] bf16-lo bits
{
    extern __shared__ __align__(16) char smem[];
    uint32_t sb = smem_u32(smem);

    int tid   = threadIdx.x;
    int w     = tid >> 5;
    int lane  = tid & 31;
    int group = blockIdx.x >> 5;    // 0..3
    int sub   = blockIdx.x & 31;    // 0..31
    int jj    = tid >> 4;           // 0..15
    int bl    = tid & 15;           // 0..15
    int j0    = sub * 16;
    int bg0   = group * 16;
    int j     = j0 + jj;
    int b     = bg0 + bl;
    int gidx  = group * 32;

    // ---- init: Whh slice (48 rows) -> bf16 hi/lo smem ----
    for (int idx = tid; idx < 48 * 512; idx += 256) {
        int r = idx >> 9;
        int k = idx & 511;
        int gg = r % 3;
        int ww = r / 3;
        float v = Whh[((size_t)(gg * H_ + j0 + ww)) * H_ + k];
        float rem;
        unsigned short hi = bf16hi_bits(v, rem);
        unsigned short lo = bf16_bits(rem);
        *(unsigned short*)(smem + r * 1040 + k * 2)          = hi;
        *(unsigned short*)(smem + OFF_WL + r * 1040 + k * 2) = lo;
    }
    // zero h smem (hh + hl) = 33280 bytes
    for (int idx = tid; idx < 33280 / 4; idx += 256)
        *(uint32_t*)(smem + OFF_HH + idx * 4) = 0u;

    float bhr = bhh[j];
    float bhz = bhh[H_ + j];
    float bhn = bhh[2 * H_ + j];
    float hold = 0.f;

    const float* gp = gates + (size_t)j * B_ + b;
    const size_t tstride = (size_t)G_ * B_;
    const size_t goff    = (size_t)H_ * B_;
    float xr = __ldcs(gp);
    float xz = __ldcs(gp + goff);
    float xn = __ldcs(gp + 2 * goff);

    // MMA warp task: warps 0-5 -> tile mt (0..2), K-half khalf (0,1)
    int mt    = w >> 1;
    int khalf = w & 1;
    int ks0   = khalf * 16;      // k-chunk base

    // B fragment addressing: lanes 0-15 -> hi buffer, 16-31 -> lo buffer;
    // one ldsm_x4 yields {bh(b0-7), bh(b8-15)} x k or hi/lo variant below.
    // We use separate x4 per buffer covering both n-halves:
    uint32_t pbH = sb + OFF_HH + (uint32_t)((lane & 15) * 1040 + (lane >> 4) * 16);
    uint32_t pbL = pbH + (OFF_HL - OFF_HH);

    // ---- preload A (W) fragments into registers ----
    unsigned Ah[16][4], Al[16][4];
    __syncthreads();
    if (w < 6) {
        uint32_t paH = sb + (uint32_t)((mt * 16 + (lane & 15)) * 1040 + (lane >> 4) * 16);
        uint32_t paL = paH + OFF_WL;
#pragma unroll
        for (int c = 0; c < 16; c++) {
            ldsm_x4(Ah[c], paH + (uint32_t)(ks0 + c) * 32);
            ldsm_x4(Al[c], paL + (uint32_t)(ks0 + c) * 32);
        }
    }

    float* hg0 = (float*)(smem + OFF_HG);
    float* hg1 = (float*)(smem + OFF_HG + HG_HALF);
    unsigned short* sth = (unsigned short*)(smem + OFF_STG);   // [16 b][16 j]
    unsigned short* stl = sth + 256;

    __syncthreads();

    for (int t = 0; t < T_; t++) {
        int par = t & 1;

        // ---- tensor-core hg = Ws @ h (warps 0-5, A in regs) ----
        if (w < 6) {
            float acc0[4] = {0.f, 0.f, 0.f, 0.f};   // b 0-7
            float acc1[4] = {0.f, 0.f, 0.f, 0.f};   // b 8-15
#pragma unroll
            for (int c = 0; c < 16; c++) {
                uint32_t ko = (uint32_t)(ks0 + c) * 32;
                unsigned bh4[4], bl4[4];
                ldsm_x4(bh4, pbH + ko);
                ldsm_x4(bl4, pbL + ko);
                unsigned bfh0[2] = { bh4[0], bh4[2] };
                unsigned bfh1[2] = { bh4[1], bh4[3] };
                unsigned bfl0[2] = { bl4[0], bl4[2] };
                unsigned bfl1[2] = { bl4[1], bl4[3] };
                mma_bf16(acc0, Ah[c], bfh0);
                mma_bf16(acc0, Ah[c], bfl0);
                mma_bf16(acc0, Al[c], bfh0);
                mma_bf16(acc1, Ah[c], bfh1);
                mma_bf16(acc1, Ah[c], bfl1);
                mma_bf16(acc1, Al[c], bfh1);
            }
            float* hgs = khalf ? hg1 : hg0;
            int r0 = mt * 16 + (lane >> 2);
            int cc = (lane & 3) * 2;
            *(float2*)&hgs[r0 * HG_STRIDE + cc]           = make_float2(acc0[0], acc0[1]);
            *(float2*)&hgs[(r0 + 8) * HG_STRIDE + cc]     = make_float2(acc0[2], acc0[3]);
            *(float2*)&hgs[r0 * HG_STRIDE + 8 + cc]       = make_float2(acc1[0], acc1[1]);
            *(float2*)&hgs[(r0 + 8) * HG_STRIDE + 8 + cc] = make_float2(acc1[2], acc1[3]);
        }
        __syncthreads();

        // ---- gate math (256 threads, one (j,b) each) ----
        int r = jj * 3;
        float ar = hg0[(r + 0) * HG_STRIDE + bl] + hg1[(r + 0) * HG_STRIDE + bl];
        float az = hg0[(r + 1) * HG_STRIDE + bl] + hg1[(r + 1) * HG_STRIDE + bl];
        float an = hg0[(r + 2) * HG_STRIDE + bl] + hg1[(r + 2) * HG_STRIDE + bl];

        float rr = 1.f / (1.f + expf(-(xr + ar + bhr)));
        float zz = 1.f / (1.f + expf(-(xz + az + bhz)));
        float nn = tanhf(xn + rr * (an + bhn));
        float hnew = (1.f - zz) * nn + zz * hold;
        hold = hnew;

        out[((size_t)t * H_ + j) * B_ + b] = hnew;
        {
            float rem;
            sth[bl * 16 + jj] = bf16hi_bits(hnew, rem);
            stl[bl * 16 + jj] = bf16_bits(rem);
        }

        // prefetch next-step gates (independent of h)
        if (t + 1 < T_) {
            const float* gq = gp + (size_t)(t + 1) * tstride;
            xr = __ldcs(gq);
            xz = __ldcs(gq + goff);
            xn = __ldcs(gq + 2 * goff);
        }

        __syncthreads();   // stage ready

        // ---- coalesced h publication: 64 threads, 16B each ----
        if (tid < 64) {
            int isLo = tid >> 5;
            int c    = tid & 31;
            int row  = c >> 1;       // b-local 0..15
            int o16  = c & 1;        // which 16B half of the 32B j-run
            const char* s = (const char*)(isLo ? stl : sth) + row * 32 + o16 * 16;
            float4 v = *(const float4*)s;
            unsigned short* dstb = isLo ? hbl : hbh;
            char* d = (char*)(dstb + par * 32768 + (size_t)(bg0 + row) * 512 + j0) + o16 * 16;
            *(float4*)d = v;
        }
        __syncthreads();   // STGs issued before arrive

        // ---- per-group release/acquire barrier over 32 CTAs ----
        if (tid == 0) {
            unsigned g = g_gen2[gidx];
            if (atom_add_release(&g_cnt[gidx], 1u) == 31u) {
                g_cnt[gidx] = 0u;
                st_release(&g_gen2[gidx], g + 1u);
            } else {
                while (ld_acquire(&g_gen2[gidx]) == g) { }
            }
        }
        __syncthreads();

        // ---- reload h bf16 hi/lo (16 b rows), coalesced ----
        {
            int row = tid >> 4;             // 0..15 local b
            int seg = (tid & 15) * 64;      // byte offset in 1024B row
            const char* srch = (const char*)(hbh + par * 32768 + (size_t)(bg0 + row) * 512) + seg;
            const char* srcl = (const char*)(hbl + par * 32768 + (size_t)(bg0 + row) * 512) + seg;
#pragma unroll
            for (int q = 0; q < 4; q++) {
                float4 v = __ldcg((const float4*)(srch + q * 16));
                *(float4*)(smem + OFF_HH + row * 1040 + seg + q * 16) = v;
            }
#pragma unroll
            for (int q = 0; q < 4; q++) {
                float4 u = __ldcg((const float4*)(srcl + q * 16));
                *(float4*)(smem + OFF_HL + row * 1040 + seg + q * 16) = u;
            }
        }
        __syncthreads();
    }
}

// =========================================================================
// hidden[l][b][h] = out_l[T-1][h][b]
// =========================================================================
__global__ __launch_bounds__(256) void k_hidden(float* __restrict__ dst) {
    int idx = blockIdx.x * 256 + threadIdx.x;
    int l  = idx >> 15;
    int rem = idx & 32767;
    int bb = rem >> 9;
    int h  = rem & 511;
    const float* src = l ? g_out1 : g_out0;
    dst[idx] = src[((size_t)(T_ - 1) * H_ + h) * B_ + bb];
}

// =========================================================================
extern "C" void kernel_launch(void* const* d_in, const int* in_sizes, int n_in,
                              void* d_out, int out_size) {
    const float* x    = (const float*)d_in[0];
    const float* Wih0 = (const float*)d_in[1];
    const float* Whh0 = (const float*)d_in[2];
    const float* bih0 = (const float*)d_in[3];
    const float* bhh0 = (const float*)d_in[4];
    const float* Wih1 = (const float*)d_in[5];
    const float* Whh1 = (const float*)d_in[6];
    const float* bih1 = (const float*)d_in[7];
    const float* bhh1 = (const float*)d_in[8];
    const float* fcw  = (const float*)d_in[9];
    const float* fcb  = (const float*)d_in[10];
    float* out = (float*)d_out;

    (void)in_sizes; (void)n_in; (void)out_size;

    cudaFuncSetAttribute(k_gru11, cudaFuncAttributeMaxDynamicSharedMemorySize,
                         GRU11_SMEM_BYTES);
    cudaFuncSetAttribute(k_gemm_mma, cudaFuncAttributeMaxDynamicSharedMemorySize,
                         TC_SMEM_TOTAL);

    float *p_gates, *p_out0, *p_out1;
    cudaGetSymbolAddress((void**)&p_gates, g_gates);
    cudaGetSymbolAddress((void**)&p_out0,  g_out0);
    cudaGetSymbolAddress((void**)&p_out1,  g_out1);
    unsigned short *hbh, *hbl;
    cudaGetSymbolAddress((void**)&hbh, g_hbh);
    cudaGetSymbolAddress((void**)&hbl, g_hbl);
    __nv_bfloat16 *w0h, *w0l, *w1h, *w1l, *wfh, *wfl, *x0h, *x0l, *x1h, *x1l;
    cudaGetSymbolAddress((void**)&w0h, g_w0h);
    cudaGetSymbolAddress((void**)&w0l, g_w0l);
    cudaGetSymbolAddress((void**)&w1h, g_w1h);
    cudaGetSymbolAddress((void**)&w1l, g_w1l);
    cudaGetSymbolAddress((void**)&wfh, g_wfh);
    cudaGetSymbolAddress((void**)&wfl, g_wfl);
    cudaGetSymbolAddress((void**)&x0h, g_x0h);
    cudaGetSymbolAddress((void**)&x0l, g_x0l);
    cudaGetSymbolAddress((void**)&x1h, g_x1h);
    cudaGetSymbolAddress((void**)&x1l, g_x1l);

    // operand prep
    k_prep_w<<<dim3(12, 4), 256>>>(Wih0, w0h, w0l, I_);
    k_prep_w<<<dim3(12, 8), 256>>>(Wih1, w1h, w1l, H_);
    k_prep_w<<<dim3(2, 8),  256>>>(fcw,  wfh, wfl, H_);
    k_prep_x<<<dim3(1024, 4), 256>>>(x);

    // layer 0
    k_gemm_mma<<<dim3(12, 512), 256, TC_SMEM_TOTAL>>>(w0h, w0l, x0h, x0l, bih0, p_gates, 4, G_, 0);
    k_gru11<<<128, 256, GRU11_SMEM_BYTES>>>(p_gates, Whh0, bhh0, p_out0, hbh, hbl);

    // layer 1
    k_prep_h<<<dim3(1024, 8), 256>>>(p_out0, x1h, x1l);
    k_gemm_mma<<<dim3(12, 512), 256, TC_SMEM_TOTAL>>>(w1h, w1l, x1h, x1l, bih1, p_gates, 8, G_, 0);
    k_gru11<<<128, 256, GRU11_SMEM_BYTES>>>(p_gates, Whh1, bhh1, p_out1, hbh, hbl);

    // FC
    k_prep_h<<<dim3(1024, 8), 256>>>(p_out1, x1h, x1l);
    k_gemm_mma<<<dim3(2, 512), 256, TC_SMEM_TOTAL>>>(wfh, wfl, x1h, x1l, fcb, out, 8, O_, 1);

    k_hidden<<<256, 256>>>(out + (size_t)B_ * T_ * O_);
}

// round 15
// speedup vs baseline: 1.0751x; 1.0751x over previous
#include <cuda_runtime.h>
#include <cuda_bf16.h>
#include <cstdint>

#define B_ 64
#define T_ 1024
#define I_ 256
#define H_ 512
#define O_ 256
#define G_ 1536   // 3*H

// ======================= scratch (device globals) =======================
__device__ float g_gates[(size_t)T_ * G_ * B_];   // [t][g][b]
__device__ float g_out0[(size_t)T_ * H_ * B_];    // [t][h][b]
__device__ float g_out1[(size_t)T_ * H_ * B_];    // [t][h][b]
__device__ unsigned g_cnt[8 * 32];                 // per-group barrier counters (padded)
__device__ unsigned g_gen2[8 * 32];                // per-group generations (padded)
__device__ unsigned short g_hbh[2 * 64 * 512];     // h bf16-hi, parity double buffer, [b][k]
__device__ unsigned short g_hbl[2 * 64 * 512];     // h bf16-lo

// pre-swizzled bf16 operand tiles (GEMM phase)
__device__ __nv_bfloat16 g_w0h[12 * 4 * 8192], g_w0l[12 * 4 * 8192];
__device__ __nv_bfloat16 g_w1h[12 * 8 * 8192], g_w1l[12 * 8 * 8192];
__device__ __nv_bfloat16 g_wfh[ 2 * 8 * 8192], g_wfl[ 2 * 8 * 8192];
__device__ __nv_bfloat16 g_x0h[(size_t)T_ * 4 * 4096], g_x0l[(size_t)T_ * 4 * 4096];
__device__ __nv_bfloat16 g_x1h[(size_t)T_ * 8 * 4096], g_x1l[(size_t)T_ * 8 * 4096];

// ======================= small helpers =======================
__device__ __forceinline__ void cp_async16(void* smem_dst, const void* gsrc) {
    unsigned s = (unsigned)__cvta_generic_to_shared(smem_dst);
    asm volatile("cp.async.ca.shared.global [%0], [%1], 16;" :: "r"(s), "l"(gsrc));
}
// L2-path (no L1 allocate) — required for cross-SM-produced data
__device__ __forceinline__ void cp_async16_cg(void* smem_dst, const void* gsrc) {
    unsigned s = (unsigned)__cvta_generic_to_shared(smem_dst);
    asm volatile("cp.async.cg.shared.global [%0], [%1], 16;" :: "r"(s), "l"(gsrc));
}
__device__ __forceinline__ void cp_commit() {
    asm volatile("cp.async.commit_group;");
}
template <int N>
__device__ __forceinline__ void cp_wait() {
    asm volatile("cp.async.wait_group %0;" :: "n"(N));
}
__device__ __forceinline__ unsigned atom_add_release(unsigned* p, unsigned v) {
    unsigned old;
    asm volatile("atom.add.release.gpu.global.u32 %0, [%1], %2;"
                 : "=r"(old) : "l"(p), "r"(v) : "memory");
    return old;
}
__device__ __forceinline__ unsigned ld_acquire(const unsigned* p) {
    unsigned v;
    asm volatile("ld.acquire.gpu.global.u32 %0, [%1];" : "=r"(v) : "l"(p) : "memory");
    return v;
}
__device__ __forceinline__ void st_release(unsigned* p, unsigned v) {
    asm volatile("st.release.gpu.global.u32 [%0], %1;" :: "l"(p), "r"(v) : "memory");
}
__device__ __forceinline__ uint32_t smem_u32(const void* p) {
    return (uint32_t)__cvta_generic_to_shared(p);
}
__host__ __device__ __forceinline__ uint32_t swz128(uint32_t o) {
    return o ^ ((o >> 3) & 0x70);
}
__device__ __forceinline__ unsigned short bf16hi_bits(float v, float& rem) {
    __nv_bfloat16 b = __float2bfloat16(v);
    rem = v - __bfloat162float(b);
    return *reinterpret_cast<unsigned short*>(&b);
}
__device__ __forceinline__ unsigned short bf16_bits(float v) {
    __nv_bfloat16 b = __float2bfloat16(v);
    return *reinterpret_cast<unsigned short*>(&b);
}

// ---- mma.sync / ldmatrix (base-target PTX) ----
__device__ __forceinline__ void ldsm_x4(unsigned* r, uint32_t addr) {
    asm volatile("ldmatrix.sync.aligned.m8n8.x4.shared.b16 {%0,%1,%2,%3}, [%4];"
        : "=r"(r[0]), "=r"(r[1]), "=r"(r[2]), "=r"(r[3]) : "r"(addr));
}
__device__ __forceinline__ void ldsm_x2(unsigned* r, uint32_t addr) {
    asm volatile("ldmatrix.sync.aligned.m8n8.x2.shared.b16 {%0,%1}, [%2];"
        : "=r"(r[0]), "=r"(r[1]) : "r"(addr));
}
__device__ __forceinline__ void mma_bf16(float* d, const unsigned* a, const unsigned* b) {
    asm volatile(
        "mma.sync.aligned.m16n8k16.row.col.f32.bf16.bf16.f32 "
        "{%0,%1,%2,%3}, {%4,%5,%6,%7}, {%8,%9}, {%0,%1,%2,%3};"
        : "+f"(d[0]), "+f"(d[1]), "+f"(d[2]), "+f"(d[3])
        : "r"(a[0]), "r"(a[1]), "r"(a[2]), "r"(a[3]), "r"(b[0]), "r"(b[1]));
}

// =========================================================================
// Prep: W [M,K] fp32 -> hi/lo bf16 SW128 tiles [mi][s][128x64]
// =========================================================================
__global__ __launch_bounds__(256) void k_prep_w(
    const float* __restrict__ src, __nv_bfloat16* __restrict__ dh,
    __nv_bfloat16* __restrict__ dl, int K)
{
    int mi = blockIdx.x, s = blockIdx.y, nS = gridDim.y;
    size_t tbase = ((size_t)mi * nS + s) * 16384;
#pragma unroll
    for (int i = 0; i < 8; i++) {
        int it  = threadIdx.x + i * 256;
        int row = it >> 4;
        int q   = it & 15;
        float4 v = *(const float4*)(src + (size_t)(mi * 128 + row) * K + s * 64 + q * 4);
        float r0, r1, r2, r3;
        ushort4 hi, lo;
        hi.x = bf16hi_bits(v.x, r0); hi.y = bf16hi_bits(v.y, r1);
        hi.z = bf16hi_bits(v.z, r2); hi.w = bf16hi_bits(v.w, r3);
        lo.x = bf16_bits(r0); lo.y = bf16_bits(r1);
        lo.z = bf16_bits(r2); lo.w = bf16_bits(r3);
        uint32_t sw = swz128((uint32_t)(row * 128 + q * 8));
        *(ushort4*)((char*)dh + tbase + sw) = hi;
        *(ushort4*)((char*)dl + tbase + sw) = lo;
    }
}

// =========================================================================
// Prep: x[b][t][k] fp32 -> hi/lo bf16 SW128 tiles [t][s][64(b)x64(k)]
// =========================================================================
__global__ __launch_bounds__(256) void k_prep_x(const float* __restrict__ x) {
    int t = blockIdx.x, s = blockIdx.y, nS = gridDim.y;
    size_t tbase = ((size_t)t * nS + s) * 8192;
#pragma unroll
    for (int i = 0; i < 4; i++) {
        int it = threadIdx.x + i * 256;
        int b  = it >> 4;
        int q  = it & 15;
        float4 v = *(const float4*)(x + ((size_t)b * T_ + t) * I_ + s * 64 + q * 4);
        float r0, r1, r2, r3;
        ushort4 hi, lo;
        hi.x = bf16hi_bits(v.x, r0); hi.y = bf16hi_bits(v.y, r1);
        hi.z = bf16hi_bits(v.z, r2); hi.w = bf16hi_bits(v.w, r3);
        lo.x = bf16_bits(r0); lo.y = bf16_bits(r1);
        lo.z = bf16_bits(r2); lo.w = bf16_bits(r3);
        uint32_t sw = swz128((uint32_t)(b * 128 + q * 8));
        *(ushort4*)((char*)g_x0h + tbase + sw) = hi;
        *(ushort4*)((char*)g_x0l + tbase + sw) = lo;
    }
}

// =========================================================================
// Prep: out[t][h][b] fp32 -> hi/lo bf16 SW128 tiles [t][s][64(b)x64(k)]
// =========================================================================
__global__ __launch_bounds__(256) void k_prep_h(
    const float* __restrict__ src, __nv_bfloat16* __restrict__ dh,
    __nv_bfloat16* __restrict__ dl)
{
    __shared__ float sm[64 * 65];
    int t = blockIdx.x, s = blockIdx.y, nS = gridDim.y;
    size_t tbase = ((size_t)t * nS + s) * 8192;
    const float* blk = src + ((size_t)t * H_ + s * 64) * B_;
#pragma unroll
    for (int i = 0; i < 16; i++) {
        int idx = threadIdx.x + i * 256;
        int k = idx >> 6, b = idx & 63;
        sm[k * 65 + b] = blk[idx];
    }
    __syncthreads();
#pragma unroll
    for (int i = 0; i < 4; i++) {
        int it = threadIdx.x + i * 256;
        int b  = it >> 4;
        int q  = it & 15;
        float v0 = sm[(q * 4 + 0) * 65 + b];
        float v1 = sm[(q * 4 + 1) * 65 + b];
        float v2 = sm[(q * 4 + 2) * 65 + b];
        float v3 = sm[(q * 4 + 3) * 65 + b];
        float r0, r1, r2, r3;
        ushort4 hi, lo;
        hi.x = bf16hi_bits(v0, r0); hi.y = bf16hi_bits(v1, r1);
        hi.z = bf16hi_bits(v2, r2); hi.w = bf16hi_bits(v3, r3);
        lo.x = bf16_bits(r0); lo.y = bf16_bits(r1);
        lo.z = bf16_bits(r2); lo.w = bf16_bits(r3);
        uint32_t sw = swz128((uint32_t)(b * 128 + q * 8));
        *(ushort4*)((char*)dh + tbase + sw) = hi;
        *(ushort4*)((char*)dl + tbase + sw) = lo;
    }
}

// =========================================================================
// mma.sync GEMM (R10 proven version: M=128 tiles)
// =========================================================================
#define TCB_BYTES 65536
#define TC_SMEM_TOTAL (1024 + 2 * TCB_BYTES)

__global__ __launch_bounds__(256) void k_gemm_mma(
    const __nv_bfloat16* __restrict__ Wh, const __nv_bfloat16* __restrict__ Wl,
    const __nv_bfloat16* __restrict__ Xh, const __nv_bfloat16* __restrict__ Xl,
    const float* __restrict__ bias, float* __restrict__ C,
    int nS, int M, int mode)
{
    extern __shared__ __align__(16) char smem[];
    uint32_t sb = smem_u32(smem);
    int tid  = threadIdx.x;
    int wid  = tid >> 5;
    int lane = tid & 31;
    int mi   = blockIdx.x;
    int m0   = mi * 128;
    int t0   = blockIdx.y * 2;

    int wm = (wid >> 1) * 32;
    int wn = (wid & 1);

    uint32_t pA = (uint32_t)((wm + (lane & 15)) * 128 + (lane >> 4) * 16);
    uint32_t rowB = (uint32_t)((lane & 7) + ((lane >> 4) & 1) * 8);
    uint32_t koffB = (uint32_t)(((lane >> 3) & 1) * 16);

    float acc[2][8][4];
#pragma unroll
    for (int i = 0; i < 2; i++)
#pragma unroll
        for (int n = 0; n < 8; n++)
#pragma unroll
            for (int c = 0; c < 4; c++) acc[i][n][c] = 0.f;

    auto issue_slab = [&](int s, int bi) {
        char* dst = smem + 1024 + bi * TCB_BYTES;
        const char* wh  = (const char*)Wh + ((size_t)mi * nS + s) * 16384;
        const char* wl  = (const char*)Wl + ((size_t)mi * nS + s) * 16384;
        const char* x0h = (const char*)Xh + ((size_t)t0 * nS + s) * 8192;
        const char* x1h = (const char*)Xh + ((size_t)(t0 + 1) * nS + s) * 8192;
        const char* x0l = (const char*)Xl + ((size_t)t0 * nS + s) * 8192;
        const char* x1l = (const char*)Xl + ((size_t)(t0 + 1) * nS + s) * 8192;
#pragma unroll
        for (int i = 0; i < 16; i++) {
            int c   = tid + i * 256;
            int reg = c >> 10;
            int off = (c & 1023) * 16;
            const char* src;
            if      (reg == 0) src = wh + off;
            else if (reg == 1) src = wl + off;
            else if (reg == 2) src = (off < 8192) ? x0h + off : x1h + (off - 8192);
            else               src = (off < 8192) ? x0l + off : x1l + (off - 8192);
            cp_async16(dst + reg * 16384 + off, src);
        }
        cp_commit();
    };

    issue_slab(0, 0);

    for (int s = 0; s < nS; s++) {
        int bi = s & 1;
        if (s + 1 < nS) {
            issue_slab(s + 1, (s + 1) & 1);
            cp_wait<1>();
        } else {
            cp_wait<0>();
        }
        __syncthreads();

        uint32_t bufb = sb + 1024 + (uint32_t)bi * TCB_BYTES;
        uint32_t aH = bufb;
        uint32_t aL = bufb + 16384;
        uint32_t bH = bufb + 32768 + (uint32_t)wn * 8192;
        uint32_t bL = bufb + 49152 + (uint32_t)wn * 8192;

#pragma unroll
        for (int ks = 0; ks < 4; ks++) {
            unsigned ah[2][4], al[2][4];
            ldsm_x4(ah[0], aH + swz128(pA + ks * 32));
            ldsm_x4(ah[1], aH + swz128(pA + 2048 + ks * 32));
            ldsm_x4(al[0], aL + swz128(pA + ks * 32));
            ldsm_x4(al[1], aL + swz128(pA + ks * 32) + 2048);
#pragma unroll
            for (int half = 0; half < 2; half++) {
                unsigned bh2[2][4], bl2[2][4];
#pragma unroll
                for (int np2 = 0; np2 < 2; np2++) {
                    int np = half * 2 + np2;
                    uint32_t pB = (uint32_t)((np * 16 + rowB) * 128) + koffB;
                    ldsm_x4(bh2[np2], bH + swz128(pB + ks * 32));
                    ldsm_x4(bl2[np2], bL + swz128(pB + ks * 32));
                }
#pragma unroll
                for (int np2 = 0; np2 < 2; np2++) {
#pragma unroll
                    for (int e = 0; e < 2; e++) {
                        int nt = half * 4 + np2 * 2 + e;
                        const unsigned* bfh = &bh2[np2][e * 2];
                        const unsigned* bfl = &bl2[np2][e * 2];
#pragma unroll
                        for (int i = 0; i < 2; i++) {
                            mma_bf16(acc[i][nt], ah[i], bfh);
                            mma_bf16(acc[i][nt], ah[i], bfl);
                            mma_bf16(acc[i][nt], al[i], bfh);
                        }
                    }
                }
            }
        }
        __syncthreads();
    }

    int qrow = lane >> 2;
    int qcol = (lane & 3) * 2;

    if (mode == 0) {
        int t = t0 + wn;
#pragma unroll
        for (int i = 0; i < 2; i++) {
            int r0 = wm + i * 16 + qrow;
            int r1 = r0 + 8;
            float bb0 = bias[m0 + r0];
            float bb1 = bias[m0 + r1];
            float* d0 = C + ((size_t)t * M + m0 + r0) * B_;
            float* d1 = C + ((size_t)t * M + m0 + r1) * B_;
#pragma unroll
            for (int nt = 0; nt < 8; nt++) {
                int col = nt * 8 + qcol;
                *(float2*)(d0 + col) = make_float2(acc[i][nt][0] + bb0, acc[i][nt][1] + bb0);
                *(float2*)(d1 + col) = make_float2(acc[i][nt][2] + bb1, acc[i][nt][3] + bb1);
            }
        }
    } else {
        float* stage = (float*)(smem + 1024);
#pragma unroll
        for (int i = 0; i < 2; i++) {
            int r0 = wm + i * 16 + qrow;
            int r1 = r0 + 8;
            float bb0 = bias[m0 + r0];
            float bb1 = bias[m0 + r1];
#pragma unroll
            for (int nt = 0; nt < 8; nt++) {
                int col = wn * 64 + nt * 8 + qcol;
                stage[r0 * 132 + col]     = acc[i][nt][0] + bb0;
                stage[r0 * 132 + col + 1] = acc[i][nt][1] + bb0;
                stage[r1 * 132 + col]     = acc[i][nt][2] + bb1;
                stage[r1 * 132 + col + 1] = acc[i][nt][3] + bb1;
            }
        }
        __syncthreads();
        int n    = tid >> 1;
        int half = tid & 1;
        int tt   = t0 + (n >> 6);
        int b2   = n & 63;
        float* dst = C + ((size_t)b2 * T_ + tt) * M + m0 + half * 64;
#pragma unroll
        for (int q = 0; q < 16; q++) {
            float4 v = make_float4(stage[(half * 64 + q * 4 + 0) * 132 + n],
                                   stage[(half * 64 + q * 4 + 1) * 132 + n],
                                   stage[(half * 64 + q * 4 + 2) * 132 + n],
                                   stage[(half * 64 + q * 4 + 3) * 132 + n]);
            *(float4*)(dst + q * 4) = v;
        }
    }
}

// =========================================================================
// Persistent GRU layer (R10 base) + cp.async split-K reload overlapped
// with next step's MMA + coalesced h publish.
// 128 CTAs = 8 batch-groups (8 b) x 16 j-subs (32 j = 96 gate-rows).
// =========================================================================
#define OFF_WL  99840
#define OFF_HH  199680
#define OFF_HL  208000
#define OFF_HG  216640
#define OFF_STG 221248
#define GRU12_SMEM_BYTES 222272

__global__ __launch_bounds__(256) void k_gru12(
    const float* __restrict__ gates,   // [t][g][b], includes b_ih
    const float* __restrict__ Whh,     // [3H][H]
    const float* __restrict__ bhh,     // [3H]
    float* __restrict__ out,           // [t][h][b]
    unsigned short* __restrict__ hbh,  // [2][64][512] bf16-hi bits
    unsigned short* __restrict__ hbl)  // [2][64][512] bf16-lo bits
{
    extern __shared__ __align__(16) char smem[];
    uint32_t sb = smem_u32(smem);

    int tid   = threadIdx.x;
    int w     = tid >> 5;
    int lane  = tid & 31;
    int group = blockIdx.x >> 4;    // 0..7
    int sub   = blockIdx.x & 15;    // 0..15
    int jj    = tid >> 3;           // 0..31
    int bl    = tid & 7;            // 0..7
    int j0    = sub * 32;
    int bg0   = group * 8;
    int j     = j0 + jj;
    int b     = bg0 + bl;
    int gidx  = group * 32;

    // ---- init: Whh slice -> bf16 hi/lo smem, row = jj*3+gate ----
    for (int idx = tid; idx < 96 * 512; idx += 256) {
        int r = idx >> 9;           // 0..95
        int k = idx & 511;
        int gg = r % 3;
        int ww = r / 3;
        float v = Whh[((size_t)(gg * H_ + j0 + ww)) * H_ + k];
        float rem;
        unsigned short hi = bf16hi_bits(v, rem);
        unsigned short lo = bf16_bits(rem);
        *(unsigned short*)(smem + r * 1040 + k * 2)          = hi;
        *(unsigned short*)(smem + OFF_WL + r * 1040 + k * 2) = lo;
    }
    // zero h smem (hh + hl)
    for (int idx = tid; idx < (2 * 8320) / 4; idx += 256)
        *(uint32_t*)(smem + OFF_HH + idx * 4) = 0u;

    float bhr = bhh[j];
    float bhz = bhh[H_ + j];
    float bhn = bhh[2 * H_ + j];
    float hold = 0.f;

    const float* gp = gates + (size_t)j * B_ + b;
    const size_t tstride = (size_t)G_ * B_;
    const size_t goff    = (size_t)H_ * B_;
    float xr = __ldcs(gp);
    float xz = __ldcs(gp + goff);
    float xn = __ldcs(gp + 2 * goff);

    // ldmatrix address patterns (byte offsets, k-chunk added in loop)
    uint32_t paH = sb + (uint32_t)((w * 16 + (lane & 15)) * 1040 + (lane >> 4) * 16);
    uint32_t paL = paH + OFF_WL;
    uint32_t pbH = sb + OFF_HH + (uint32_t)((lane & 7) * 1040 + ((lane >> 3) & 1) * 16);
    uint32_t pbL = pbH + (OFF_HL - OFF_HH);
    float* hg = (float*)(smem + OFF_HG);
    unsigned short* sth = (unsigned short*)(smem + OFF_STG);   // [8 b][32 jj]
    unsigned short* stl = sth + 256;

    // reload thread mapping: threads 0-127 -> hi, 128-255 -> lo
    int rl_lo  = tid >> 7;                 // 0 = hi, 1 = lo
    int rl_row = (tid >> 4) & 7;           // local b 0..7
    int rl_seg = (tid & 15) * 32;          // 0..480 within 512B half

    __syncthreads();

    for (int t = 0; t < T_; t++) {
        int par = t & 1;

        // ---- wait first reload half, then MMA k 0..15 ----
        if (t > 0) cp_wait<1>();
        __syncthreads();

        float acc[4] = {0.f, 0.f, 0.f, 0.f};
        if (w < 6) {
#pragma unroll
            for (int ks = 0; ks < 16; ks++) {
                uint32_t ko = (uint32_t)ks * 32;
                unsigned ah[4], al[4], bh2[2], bl2[2];
                ldsm_x4(ah, paH + ko);
                ldsm_x4(al, paL + ko);
                ldsm_x2(bh2, pbH + ko);
                ldsm_x2(bl2, pbL + ko);
                mma_bf16(acc, ah, bh2);
                mma_bf16(acc, ah, bl2);
                mma_bf16(acc, al, bh2);
            }
        }

        // ---- wait second reload half, then MMA k 16..31 ----
        if (t > 0) cp_wait<0>();
        __syncthreads();

        if (w < 6) {
#pragma unroll
            for (int ks = 16; ks < 32; ks++) {
                uint32_t ko = (uint32_t)ks * 32;
                unsigned ah[4], al[4], bh2[2], bl2[2];
                ldsm_x4(ah, paH + ko);
                ldsm_x4(al, paL + ko);
                ldsm_x2(bh2, pbH + ko);
                ldsm_x2(bl2, pbL + ko);
                mma_bf16(acc, ah, bh2);
                mma_bf16(acc, ah, bl2);
                mma_bf16(acc, al, bh2);
            }
            int r0 = w * 16 + (lane >> 2);
            *(float2*)&hg[r0 * 12 + (lane & 3) * 2]       = make_float2(acc[0], acc[1]);
            *(float2*)&hg[(r0 + 8) * 12 + (lane & 3) * 2] = make_float2(acc[2], acc[3]);
        }
        __syncthreads();

        // ---- gate math (all 256 threads, one (j,b) each) ----
        float ar = hg[(jj * 3 + 0) * 12 + bl];
        float az = hg[(jj * 3 + 1) * 12 + bl];
        float an = hg[(jj * 3 + 2) * 12 + bl];

        float r = 1.f / (1.f + expf(-(xr + ar + bhr)));
        float z = 1.f / (1.f + expf(-(xz + az + bhz)));
        float n = tanhf(xn + r * (an + bhn));
        float hnew = (1.f - z) * n + z * hold;
        hold = hnew;

        out[((size_t)t * H_ + j) * B_ + b] = hnew;
        {
            float rem;
            sth[bl * 32 + jj] = bf16hi_bits(hnew, rem);
            stl[bl * 32 + jj] = bf16_bits(rem);
        }

        // prefetch next-step gates (independent of h)
        if (t + 1 < T_) {
            const float* gq = gp + (size_t)(t + 1) * tstride;
            xr = __ldcs(gq);
            xz = __ldcs(gq + goff);
            xn = __ldcs(gq + 2 * goff);
        }

        __syncthreads();   // stage ready

        // ---- coalesced h publication: 64 threads, 16B each ----
        if (tid < 64) {
            int isLo = tid >> 5;
            int c    = tid & 31;
            int row  = c >> 2;       // local b 0..7
            int o16  = c & 3;        // 16B chunk within 64B j-run
            const char* s = (const char*)(isLo ? stl : sth) + row * 64 + o16 * 16;
            float4 v = *(const float4*)s;
            unsigned short* dstb = isLo ? hbl : hbh;
            char* d = (char*)(dstb + par * 32768 + (size_t)(bg0 + row) * 512 + j0) + o16 * 16;
            *(float4*)d = v;
        }
        __syncthreads();   // STGs issued before arrive

        // ---- per-group release/acquire barrier over 16 CTAs ----
        if (tid == 0) {
            unsigned g = g_gen2[gidx];
            if (atom_add_release(&g_cnt[gidx], 1u) == 15u) {
                g_cnt[gidx] = 0u;
                st_release(&g_gen2[gidx], g + 1u);
            } else {
                while (ld_acquire(&g_gen2[gidx]) == g) { }
            }
        }
        __syncthreads();

        // ---- issue split-K cp.async reload (waited at next iter top) ----
        if (t + 1 < T_) {
            const unsigned short* srcb = rl_lo ? hbl : hbh;
            const char* src = (const char*)(srcb + par * 32768 + (size_t)(bg0 + rl_row) * 512);
            char* dst = smem + (rl_lo ? OFF_HL : OFF_HH) + rl_row * 1040;
            // phase 1: k 0..255 (bytes 0..511)
            cp_async16_cg(dst + rl_seg,      src + rl_seg);
            cp_async16_cg(dst + rl_seg + 16, src + rl_seg + 16);
            cp_commit();
            // phase 2: k 256..511 (bytes 512..1023)
            cp_async16_cg(dst + 512 + rl_seg,      src + 512 + rl_seg);
            cp_async16_cg(dst + 512 + rl_seg + 16, src + 512 + rl_seg + 16);
            cp_commit();
        }
    }
}

// =========================================================================
// hidden[l][b][h] = out_l[T-1][h][b]
// =========================================================================
__global__ __launch_bounds__(256) void k_hidden(float* __restrict__ dst) {
    int idx = blockIdx.x * 256 + threadIdx.x;
    int l  = idx >> 15;
    int rem = idx & 32767;
    int bb = rem >> 9;
    int h  = rem & 511;
    const float* src = l ? g_out1 : g_out0;
    dst[idx] = src[((size_t)(T_ - 1) * H_ + h) * B_ + bb];
}

// =========================================================================
extern "C" void kernel_launch(void* const* d_in, const int* in_sizes, int n_in,
                              void* d_out, int out_size) {
    const float* x    = (const float*)d_in[0];
    const float* Wih0 = (const float*)d_in[1];
    const float* Whh0 = (const float*)d_in[2];
    const float* bih0 = (const float*)d_in[3];
    const float* bhh0 = (const float*)d_in[4];
    const float* Wih1 = (const float*)d_in[5];
    const float* Whh1 = (const float*)d_in[6];
    const float* bih1 = (const float*)d_in[7];
    const float* bhh1 = (const float*)d_in[8];
    const float* fcw  = (const float*)d_in[9];
    const float* fcb  = (const float*)d_in[10];
    float* out = (float*)d_out;

    (void)in_sizes; (void)n_in; (void)out_size;

    cudaFuncSetAttribute(k_gru12, cudaFuncAttributeMaxDynamicSharedMemorySize,
                         GRU12_SMEM_BYTES);
    cudaFuncSetAttribute(k_gemm_mma, cudaFuncAttributeMaxDynamicSharedMemorySize,
                         TC_SMEM_TOTAL);

    float *p_gates, *p_out0, *p_out1;
    cudaGetSymbolAddress((void**)&p_gates, g_gates);
    cudaGetSymbolAddress((void**)&p_out0,  g_out0);
    cudaGetSymbolAddress((void**)&p_out1,  g_out1);
    unsigned short *hbh, *hbl;
    cudaGetSymbolAddress((void**)&hbh, g_hbh);
    cudaGetSymbolAddress((void**)&hbl, g_hbl);
    __nv_bfloat16 *w0h, *w0l, *w1h, *w1l, *wfh, *wfl, *x0h, *x0l, *x1h, *x1l;
    cudaGetSymbolAddress((void**)&w0h, g_w0h);
    cudaGetSymbolAddress((void**)&w0l, g_w0l);
    cudaGetSymbolAddress((void**)&w1h, g_w1h);
    cudaGetSymbolAddress((void**)&w1l, g_w1l);
    cudaGetSymbolAddress((void**)&wfh, g_wfh);
    cudaGetSymbolAddress((void**)&wfl, g_wfl);
    cudaGetSymbolAddress((void**)&x0h, g_x0h);
    cudaGetSymbolAddress((void**)&x0l, g_x0l);
    cudaGetSymbolAddress((void**)&x1h, g_x1h);
    cudaGetSymbolAddress((void**)&x1l, g_x1l);

    // operand prep
    k_prep_w<<<dim3(12, 4), 256>>>(Wih0, w0h, w0l, I_);
    k_prep_w<<<dim3(12, 8), 256>>>(Wih1, w1h, w1l, H_);
    k_prep_w<<<dim3(2, 8),  256>>>(fcw,  wfh, wfl, H_);
    k_prep_x<<<dim3(1024, 4), 256>>>(x);

    // layer 0
    k_gemm_mma<<<dim3(12, 512), 256, TC_SMEM_TOTAL>>>(w0h, w0l, x0h, x0l, bih0, p_gates, 4, G_, 0);
    k_gru12<<<128, 256, GRU12_SMEM_BYTES>>>(p_gates, Whh0, bhh0, p_out0, hbh, hbl);

    // layer 1
    k_prep_h<<<dim3(1024, 8), 256>>>(p_out0, x1h, x1l);
    k_gemm_mma<<<dim3(12, 512), 256, TC_SMEM_TOTAL>>>(w1h, w1l, x1h, x1l, bih1, p_gates, 8, G_, 0);
    k_gru12<<<128, 256, GRU12_SMEM_BYTES>>>(p_gates, Whh1, bhh1, p_out1, hbh, hbl);

    // FC
    k_prep_h<<<dim3(1024, 8), 256>>>(p_out1, x1h, x1l);
    k_gemm_mma<<<dim3(2, 512), 256, TC_SMEM_TOTAL>>>(wfh, wfl, x1h, x1l, fcb, out, 8, O_, 1);

    k_hidden<<<256, 256>>>(out + (size_t)B_ * T_ * O_);
}

// round 16
// speedup vs baseline: 1.2008x; 1.1169x over previous
#include <cuda_runtime.h>
#include <cuda_bf16.h>
#include <cstdint>

#define B_ 64
#define T_ 1024
#define I_ 256
#define H_ 512
#define O_ 256
#define G_ 1536   // 3*H

// ======================= scratch (device globals) =======================
__device__ float g_gates[(size_t)T_ * G_ * B_];   // [t][g][b]
__device__ float g_out0[(size_t)T_ * H_ * B_];    // [t][h][b]
__device__ float g_out1[(size_t)T_ * H_ * B_];    // [t][h][b]
__device__ unsigned g_cnt[8 * 32];                 // per-group split counters (monotonic)
__device__ unsigned short g_hbh[2 * 64 * 512];     // h bf16-hi, parity double buffer, [b][k]
__device__ unsigned short g_hbl[2 * 64 * 512];     // h bf16-lo

// pre-swizzled bf16 operand tiles (GEMM phase)
__device__ __nv_bfloat16 g_w0h[12 * 4 * 8192], g_w0l[12 * 4 * 8192];
__device__ __nv_bfloat16 g_w1h[12 * 8 * 8192], g_w1l[12 * 8 * 8192];
__device__ __nv_bfloat16 g_wfh[ 2 * 8 * 8192], g_wfl[ 2 * 8 * 8192];
__device__ __nv_bfloat16 g_x0h[(size_t)T_ * 4 * 4096], g_x0l[(size_t)T_ * 4 * 4096];
__device__ __nv_bfloat16 g_x1h[(size_t)T_ * 8 * 4096], g_x1l[(size_t)T_ * 8 * 4096];

// ======================= small helpers =======================
__device__ __forceinline__ void cp_async16(void* smem_dst, const void* gsrc) {
    unsigned s = (unsigned)__cvta_generic_to_shared(smem_dst);
    asm volatile("cp.async.ca.shared.global [%0], [%1], 16;" :: "r"(s), "l"(gsrc));
}
// L2-path (no L1 allocate) — required for cross-SM-produced data
__device__ __forceinline__ void cp_async16_cg(void* smem_dst, const void* gsrc) {
    unsigned s = (unsigned)__cvta_generic_to_shared(smem_dst);
    asm volatile("cp.async.cg.shared.global [%0], [%1], 16;" :: "r"(s), "l"(gsrc));
}
__device__ __forceinline__ void cp_commit() {
    asm volatile("cp.async.commit_group;");
}
template <int N>
__device__ __forceinline__ void cp_wait() {
    asm volatile("cp.async.wait_group %0;" :: "n"(N));
}
__device__ __forceinline__ unsigned atom_add_release(unsigned* p, unsigned v) {
    unsigned old;
    asm volatile("atom.add.release.gpu.global.u32 %0, [%1], %2;"
                 : "=r"(old) : "l"(p), "r"(v) : "memory");
    return old;
}
__device__ __forceinline__ unsigned ld_acquire(const unsigned* p) {
    unsigned v;
    asm volatile("ld.acquire.gpu.global.u32 %0, [%1];" : "=r"(v) : "l"(p) : "memory");
    return v;
}
__device__ __forceinline__ uint32_t smem_u32(const void* p) {
    return (uint32_t)__cvta_generic_to_shared(p);
}
__host__ __device__ __forceinline__ uint32_t swz128(uint32_t o) {
    return o ^ ((o >> 3) & 0x70);
}
__device__ __forceinline__ unsigned short bf16hi_bits(float v, float& rem) {
    __nv_bfloat16 b = __float2bfloat16(v);
    rem = v - __bfloat162float(b);
    return *reinterpret_cast<unsigned short*>(&b);
}
__device__ __forceinline__ unsigned short bf16_bits(float v) {
    __nv_bfloat16 b = __float2bfloat16(v);
    return *reinterpret_cast<unsigned short*>(&b);
}
// fast activations: ex2.approx + rcp.approx (~1e-6 rel err, NOT tanh.approx)
__device__ __forceinline__ float fast_sigmoid(float x) {
    float e, r;
    asm("ex2.approx.f32 %0, %1;" : "=f"(e) : "f"(-1.4426950408889634f * x));
    asm("rcp.approx.f32 %0, %1;" : "=f"(r) : "f"(1.f + e));
    return r;
}
__device__ __forceinline__ float fast_tanh(float x) {
    float e, r;
    asm("ex2.approx.f32 %0, %1;" : "=f"(e) : "f"(2.8853900817779268f * x));
    asm("rcp.approx.f32 %0, %1;" : "=f"(r) : "f"(1.f + e));
    return 1.f - 2.f * r;   // (e-1)/(e+1)
}

// ---- mma.sync / ldmatrix (base-target PTX) ----
__device__ __forceinline__ void ldsm_x4(unsigned* r, uint32_t addr) {
    asm volatile("ldmatrix.sync.aligned.m8n8.x4.shared.b16 {%0,%1,%2,%3}, [%4];"
        : "=r"(r[0]), "=r"(r[1]), "=r"(r[2]), "=r"(r[3]) : "r"(addr));
}
__device__ __forceinline__ void ldsm_x2(unsigned* r, uint32_t addr) {
    asm volatile("ldmatrix.sync.aligned.m8n8.x2.shared.b16 {%0,%1}, [%2];"
        : "=r"(r[0]), "=r"(r[1]) : "r"(addr));
}
__device__ __forceinline__ void mma_bf16(float* d, const unsigned* a, const unsigned* b) {
    asm volatile(
        "mma.sync.aligned.m16n8k16.row.col.f32.bf16.bf16.f32 "
        "{%0,%1,%2,%3}, {%4,%5,%6,%7}, {%8,%9}, {%0,%1,%2,%3};"
        : "+f"(d[0]), "+f"(d[1]), "+f"(d[2]), "+f"(d[3])
        : "r"(a[0]), "r"(a[1]), "r"(a[2]), "r"(a[3]), "r"(b[0]), "r"(b[1]));
}

// =========================================================================
// Zero the barrier counters (before each recurrent launch; graph-safe)
// =========================================================================
__global__ void k_zero() {
    g_cnt[threadIdx.x] = 0u;
}

// =========================================================================
// Prep: W [M,K] fp32 -> hi/lo bf16 SW128 tiles [mi][s][128x64]
// =========================================================================
__global__ __launch_bounds__(256) void k_prep_w(
    const float* __restrict__ src, __nv_bfloat16* __restrict__ dh,
    __nv_bfloat16* __restrict__ dl, int K)
{
    int mi = blockIdx.x, s = blockIdx.y, nS = gridDim.y;
    size_t tbase = ((size_t)mi * nS + s) * 16384;
#pragma unroll
    for (int i = 0; i < 8; i++) {
        int it  = threadIdx.x + i * 256;
        int row = it >> 4;
        int q   = it & 15;
        float4 v = *(const float4*)(src + (size_t)(mi * 128 + row) * K + s * 64 + q * 4);
        float r0, r1, r2, r3;
        ushort4 hi, lo;
        hi.x = bf16hi_bits(v.x, r0); hi.y = bf16hi_bits(v.y, r1);
        hi.z = bf16hi_bits(v.z, r2); hi.w = bf16hi_bits(v.w, r3);
        lo.x = bf16_bits(r0); lo.y = bf16_bits(r1);
        lo.z = bf16_bits(r2); lo.w = bf16_bits(r3);
        uint32_t sw = swz128((uint32_t)(row * 128 + q * 8));
        *(ushort4*)((char*)dh + tbase + sw) = hi;
        *(ushort4*)((char*)dl + tbase + sw) = lo;
    }
}

// =========================================================================
// Prep: x[b][t][k] fp32 -> hi/lo bf16 SW128 tiles [t][s][64(b)x64(k)]
// =========================================================================
__global__ __launch_bounds__(256) void k_prep_x(const float* __restrict__ x) {
    int t = blockIdx.x, s = blockIdx.y, nS = gridDim.y;
    size_t tbase = ((size_t)t * nS + s) * 8192;
#pragma unroll
    for (int i = 0; i < 4; i++) {
        int it = threadIdx.x + i * 256;
        int b  = it >> 4;
        int q  = it & 15;
        float4 v = *(const float4*)(x + ((size_t)b * T_ + t) * I_ + s * 64 + q * 4);
        float r0, r1, r2, r3;
        ushort4 hi, lo;
        hi.x = bf16hi_bits(v.x, r0); hi.y = bf16hi_bits(v.y, r1);
        hi.z = bf16hi_bits(v.z, r2); hi.w = bf16hi_bits(v.w, r3);
        lo.x = bf16_bits(r0); lo.y = bf16_bits(r1);
        lo.z = bf16_bits(r2); lo.w = bf16_bits(r3);
        uint32_t sw = swz128((uint32_t)(b * 128 + q * 8));
        *(ushort4*)((char*)g_x0h + tbase + sw) = hi;
        *(ushort4*)((char*)g_x0l + tbase + sw) = lo;
    }
}

// =========================================================================
// Prep: out[t][h][b] fp32 -> hi/lo bf16 SW128 tiles [t][s][64(b)x64(k)]
// =========================================================================
__global__ __launch_bounds__(256) void k_prep_h(
    const float* __restrict__ src, __nv_bfloat16* __restrict__ dh,
    __nv_bfloat16* __restrict__ dl)
{
    __shared__ float sm[64 * 65];
    int t = blockIdx.x, s = blockIdx.y, nS = gridDim.y;
    size_t tbase = ((size_t)t * nS + s) * 8192;
    const float* blk = src + ((size_t)t * H_ + s * 64) * B_;
#pragma unroll
    for (int i = 0; i < 16; i++) {
        int idx = threadIdx.x + i * 256;
        int k = idx >> 6, b = idx & 63;
        sm[k * 65 + b] = blk[idx];
    }
    __syncthreads();
#pragma unroll
    for (int i = 0; i < 4; i++) {
        int it = threadIdx.x + i * 256;
        int b  = it >> 4;
        int q  = it & 15;
        float v0 = sm[(q * 4 + 0) * 65 + b];
        float v1 = sm[(q * 4 + 1) * 65 + b];
        float v2 = sm[(q * 4 + 2) * 65 + b];
        float v3 = sm[(q * 4 + 3) * 65 + b];
        float r0, r1, r2, r3;
        ushort4 hi, lo;
        hi.x = bf16hi_bits(v0, r0); hi.y = bf16hi_bits(v1, r1);
        hi.z = bf16hi_bits(v2, r2); hi.w = bf16hi_bits(v3, r3);
        lo.x = bf16_bits(r0); lo.y = bf16_bits(r1);
        lo.z = bf16_bits(r2); lo.w = bf16_bits(r3);
        uint32_t sw = swz128((uint32_t)(b * 128 + q * 8));
        *(ushort4*)((char*)dh + tbase + sw) = hi;
        *(ushort4*)((char*)dl + tbase + sw) = lo;
    }
}

// =========================================================================
// mma.sync GEMM (R10/R15 proven version: M=128 tiles)
// =========================================================================
#define TCB_BYTES 65536
#define TC_SMEM_TOTAL (1024 + 2 * TCB_BYTES)

__global__ __launch_bounds__(256) void k_gemm_mma(
    const __nv_bfloat16* __restrict__ Wh, const __nv_bfloat16* __restrict__ Wl,
    const __nv_bfloat16* __restrict__ Xh, const __nv_bfloat16* __restrict__ Xl,
    const float* __restrict__ bias, float* __restrict__ C,
    int nS, int M, int mode)
{
    extern __shared__ __align__(16) char smem[];
    uint32_t sb = smem_u32(smem);
    int tid  = threadIdx.x;
    int wid  = tid >> 5;
    int lane = tid & 31;
    int mi   = blockIdx.x;
    int m0   = mi * 128;
    int t0   = blockIdx.y * 2;

    int wm = (wid >> 1) * 32;
    int wn = (wid & 1);

    uint32_t pA = (uint32_t)((wm + (lane & 15)) * 128 + (lane >> 4) * 16);
    uint32_t rowB = (uint32_t)((lane & 7) + ((lane >> 4) & 1) * 8);
    uint32_t koffB = (uint32_t)(((lane >> 3) & 1) * 16);

    float acc[2][8][4];
#pragma unroll
    for (int i = 0; i < 2; i++)
#pragma unroll
        for (int n = 0; n < 8; n++)
#pragma unroll
            for (int c = 0; c < 4; c++) acc[i][n][c] = 0.f;

    auto issue_slab = [&](int s, int bi) {
        char* dst = smem + 1024 + bi * TCB_BYTES;
        const char* wh  = (const char*)Wh + ((size_t)mi * nS + s) * 16384;
        const char* wl  = (const char*)Wl + ((size_t)mi * nS + s) * 16384;
        const char* x0h = (const char*)Xh + ((size_t)t0 * nS + s) * 8192;
        const char* x1h = (const char*)Xh + ((size_t)(t0 + 1) * nS + s) * 8192;
        const char* x0l = (const char*)Xl + ((size_t)t0 * nS + s) * 8192;
        const char* x1l = (const char*)Xl + ((size_t)(t0 + 1) * nS + s) * 8192;
#pragma unroll
        for (int i = 0; i < 16; i++) {
            int c   = tid + i * 256;
            int reg = c >> 10;
            int off = (c & 1023) * 16;
            const char* src;
            if      (reg == 0) src = wh + off;
            else if (reg == 1) src = wl + off;
            else if (reg == 2) src = (off < 8192) ? x0h + off : x1h + (off - 8192);
            else               src = (off < 8192) ? x0l + off : x1l + (off - 8192);
            cp_async16(dst + reg * 16384 + off, src);
        }
        cp_commit();
    };

    issue_slab(0, 0);

    for (int s = 0; s < nS; s++) {
        int bi = s & 1;
        if (s + 1 < nS) {
            issue_slab(s + 1, (s + 1) & 1);
            cp_wait<1>();
        } else {
            cp_wait<0>();
        }
        __syncthreads();

        uint32_t bufb = sb + 1024 + (uint32_t)bi * TCB_BYTES;
        uint32_t aH = bufb;
        uint32_t aL = bufb + 16384;
        uint32_t bH = bufb + 32768 + (uint32_t)wn * 8192;
        uint32_t bL = bufb + 49152 + (uint32_t)wn * 8192;

#pragma unroll
        for (int ks = 0; ks < 4; ks++) {
            unsigned ah[2][4], al[2][4];
            ldsm_x4(ah[0], aH + swz128(pA + ks * 32));
            ldsm_x4(ah[1], aH + swz128(pA + 2048 + ks * 32));
            ldsm_x4(al[0], aL + swz128(pA + ks * 32));
            ldsm_x4(al[1], aL + swz128(pA + 2048 + ks * 32));
#pragma unroll
            for (int half = 0; half < 2; half++) {
                unsigned bh2[2][4], bl2[2][4];
#pragma unroll
                for (int np2 = 0; np2 < 2; np2++) {
                    int np = half * 2 + np2;
                    uint32_t pB = (uint32_t)((np * 16 + rowB) * 128) + koffB;
                    ldsm_x4(bh2[np2], bH + swz128(pB + ks * 32));
                    ldsm_x4(bl2[np2], bL + swz128(pB + ks * 32));
                }
#pragma unroll
                for (int np2 = 0; np2 < 2; np2++) {
#pragma unroll
                    for (int e = 0; e < 2; e++) {
                        int nt = half * 4 + np2 * 2 + e;
                        const unsigned* bfh = &bh2[np2][e * 2];
                        const unsigned* bfl = &bl2[np2][e * 2];
#pragma unroll
                        for (int i = 0; i < 2; i++) {
                            mma_bf16(acc[i][nt], ah[i], bfh);
                            mma_bf16(acc[i][nt], ah[i], bfl);
                            mma_bf16(acc[i][nt], al[i], bfh);
                        }
                    }
                }
            }
        }
        __syncthreads();
    }

    int qrow = lane >> 2;
    int qcol = (lane & 3) * 2;

    if (mode == 0) {
        int t = t0 + wn;
#pragma unroll
        for (int i = 0; i < 2; i++) {
            int r0 = wm + i * 16 + qrow;
            int r1 = r0 + 8;
            float bb0 = bias[m0 + r0];
            float bb1 = bias[m0 + r1];
            float* d0 = C + ((size_t)t * M + m0 + r0) * B_;
            float* d1 = C + ((size_t)t * M + m0 + r1) * B_;
#pragma unroll
            for (int nt = 0; nt < 8; nt++) {
                int col = nt * 8 + qcol;
                *(float2*)(d0 + col) = make_float2(acc[i][nt][0] + bb0, acc[i][nt][1] + bb0);
                *(float2*)(d1 + col) = make_float2(acc[i][nt][2] + bb1, acc[i][nt][3] + bb1);
            }
        }
    } else {
        float* stage = (float*)(smem + 1024);
#pragma unroll
        for (int i = 0; i < 2; i++) {
            int r0 = wm + i * 16 + qrow;
            int r1 = r0 + 8;
            float bb0 = bias[m0 + r0];
            float bb1 = bias[m0 + r1];
#pragma unroll
            for (int nt = 0; nt < 8; nt++) {
                int col = wn * 64 + nt * 8 + qcol;
                stage[r0 * 132 + col]     = acc[i][nt][0] + bb0;
                stage[r0 * 132 + col + 1] = acc[i][nt][1] + bb0;
                stage[r1 * 132 + col]     = acc[i][nt][2] + bb1;
                stage[r1 * 132 + col + 1] = acc[i][nt][3] + bb1;
            }
        }
        __syncthreads();
        int n    = tid >> 1;
        int half = tid & 1;
        int tt   = t0 + (n >> 6);
        int b2   = n & 63;
        float* dst = C + ((size_t)b2 * T_ + tt) * M + m0 + half * 64;
#pragma unroll
        for (int q = 0; q < 16; q++) {
            float4 v = make_float4(stage[(half * 64 + q * 4 + 0) * 132 + n],
                                   stage[(half * 64 + q * 4 + 1) * 132 + n],
                                   stage[(half * 64 + q * 4 + 2) * 132 + n],
                                   stage[(half * 64 + q * 4 + 3) * 132 + n]);
            *(float4*)(dst + q * 4) = v;
        }
    }
}

// =========================================================================
// Persistent GRU layer (R15 base) + SPLIT-HALF barrier (earlier phase-1
// reload) + fast activations.
// 128 CTAs = 8 batch-groups (8 b) x 16 j-subs (32 j = 96 gate-rows).
// Counters: monotonic; subs 0-7 arrive on cnt[gidx], subs 8-15 on
// cnt[gidx+16]. Wait cnt0>=8(t+1) -> phase-1 reload (k 0..255, produced by
// subs 0-7); wait cnt1 -> phase-2 (k 256..511).
// =========================================================================
#define OFF_WL  99840
#define OFF_HH  199680
#define OFF_HL  208000
#define OFF_HG  216640
#define OFF_STG 221248
#define GRU13_SMEM_BYTES 222272

__global__ __launch_bounds__(256) void k_gru13(
    const float* __restrict__ gates,   // [t][g][b], includes b_ih
    const float* __restrict__ Whh,     // [3H][H]
    const float* __restrict__ bhh,     // [3H]
    float* __restrict__ out,           // [t][h][b]
    unsigned short* __restrict__ hbh,  // [2][64][512] bf16-hi bits
    unsigned short* __restrict__ hbl)  // [2][64][512] bf16-lo bits
{
    extern __shared__ __align__(16) char smem[];
    uint32_t sb = smem_u32(smem);

    int tid   = threadIdx.x;
    int w     = tid >> 5;
    int lane  = tid & 31;
    int group = blockIdx.x >> 4;    // 0..7
    int sub   = blockIdx.x & 15;    // 0..15
    int jj    = tid >> 3;           // 0..31
    int bl    = tid & 7;            // 0..7
    int j0    = sub * 32;
    int bg0   = group * 8;
    int j     = j0 + jj;
    int b     = bg0 + bl;
    unsigned* cnt0 = &g_cnt[group * 32];        // subs 0-7 (k 0..255)
    unsigned* cnt1 = &g_cnt[group * 32 + 16];   // subs 8-15 (k 256..511)
    unsigned* cown = (sub < 8) ? cnt0 : cnt1;

    // ---- init: Whh slice -> bf16 hi/lo smem, row = jj*3+gate ----
    for (int idx = tid; idx < 96 * 512; idx += 256) {
        int r = idx >> 9;           // 0..95
        int k = idx & 511;
        int gg = r % 3;
        int ww = r / 3;
        float v = Whh[((size_t)(gg * H_ + j0 + ww)) * H_ + k];
        float rem;
        unsigned short hi = bf16hi_bits(v, rem);
        unsigned short lo = bf16_bits(rem);
        *(unsigned short*)(smem + r * 1040 + k * 2)          = hi;
        *(unsigned short*)(smem + OFF_WL + r * 1040 + k * 2) = lo;
    }
    // zero h smem (hh + hl)
    for (int idx = tid; idx < (2 * 8320) / 4; idx += 256)
        *(uint32_t*)(smem + OFF_HH + idx * 4) = 0u;

    float bhr = bhh[j];
    float bhz = bhh[H_ + j];
    float bhn = bhh[2 * H_ + j];
    float hold = 0.f;

    const float* gp = gates + (size_t)j * B_ + b;
    const size_t tstride = (size_t)G_ * B_;
    const size_t goff    = (size_t)H_ * B_;
    float xr = __ldcs(gp);
    float xz = __ldcs(gp + goff);
    float xn = __ldcs(gp + 2 * goff);

    // ldmatrix address patterns (byte offsets, k-chunk added in loop)
    uint32_t paH = sb + (uint32_t)((w * 16 + (lane & 15)) * 1040 + (lane >> 4) * 16);
    uint32_t paL = paH + OFF_WL;
    uint32_t pbH = sb + OFF_HH + (uint32_t)((lane & 7) * 1040 + ((lane >> 3) & 1) * 16);
    uint32_t pbL = pbH + (OFF_HL - OFF_HH);
    float* hg = (float*)(smem + OFF_HG);
    unsigned short* sth = (unsigned short*)(smem + OFF_STG);   // [8 b][32 jj]
    unsigned short* stl = sth + 256;

    // reload thread mapping: threads 0-127 -> hi, 128-255 -> lo
    int rl_lo  = tid >> 7;                 // 0 = hi, 1 = lo
    int rl_row = (tid >> 4) & 7;           // local b 0..7
    int rl_seg = (tid & 15) * 32;          // 0..480 within 512B half

    __syncthreads();

    for (int t = 0; t < T_; t++) {
        int par = t & 1;

        // ---- wait first reload half, then MMA k 0..15 ----
        if (t > 0) cp_wait<1>();
        __syncthreads();

        float acc[4] = {0.f, 0.f, 0.f, 0.f};
        if (w < 6) {
#pragma unroll
            for (int ks = 0; ks < 16; ks++) {
                uint32_t ko = (uint32_t)ks * 32;
                unsigned ah[4], al[4], bh2[2], bl2[2];
                ldsm_x4(ah, paH + ko);
                ldsm_x4(al, paL + ko);
                ldsm_x2(bh2, pbH + ko);
                ldsm_x2(bl2, pbL + ko);
                mma_bf16(acc, ah, bh2);
                mma_bf16(acc, ah, bl2);
                mma_bf16(acc, al, bh2);
            }
        }

        // ---- wait second reload half, then MMA k 16..31 ----
        if (t > 0) cp_wait<0>();
        __syncthreads();

        if (w < 6) {
#pragma unroll
            for (int ks = 16; ks < 32; ks++) {
                uint32_t ko = (uint32_t)ks * 32;
                unsigned ah[4], al[4], bh2[2], bl2[2];
                ldsm_x4(ah, paH + ko);
                ldsm_x4(al, paL + ko);
                ldsm_x2(bh2, pbH + ko);
                ldsm_x2(bl2, pbL + ko);
                mma_bf16(acc, ah, bh2);
                mma_bf16(acc, ah, bl2);
                mma_bf16(acc, al, bh2);
            }
            int r0 = w * 16 + (lane >> 2);
            *(float2*)&hg[r0 * 12 + (lane & 3) * 2]       = make_float2(acc[0], acc[1]);
            *(float2*)&hg[(r0 + 8) * 12 + (lane & 3) * 2] = make_float2(acc[2], acc[3]);
        }
        __syncthreads();

        // ---- gate math (all 256 threads, one (j,b) each) ----
        float ar = hg[(jj * 3 + 0) * 12 + bl];
        float az = hg[(jj * 3 + 1) * 12 + bl];
        float an = hg[(jj * 3 + 2) * 12 + bl];

        float r = fast_sigmoid(xr + ar + bhr);
        float z = fast_sigmoid(xz + az + bhz);
        float n = fast_tanh(xn + r * (an + bhn));
        float hnew = (1.f - z) * n + z * hold;
        hold = hnew;

        out[((size_t)t * H_ + j) * B_ + b] = hnew;
        {
            float rem;
            sth[bl * 32 + jj] = bf16hi_bits(hnew, rem);
            stl[bl * 32 + jj] = bf16_bits(rem);
        }

        // prefetch next-step gates (independent of h)
        if (t + 1 < T_) {
            const float* gq = gp + (size_t)(t + 1) * tstride;
            xr = __ldcs(gq);
            xz = __ldcs(gq + goff);
            xn = __ldcs(gq + 2 * goff);
        }

        __syncthreads();   // stage ready

        // ---- coalesced h publication: 64 threads, 16B each ----
        if (tid < 64) {
            int isLo = tid >> 5;
            int c    = tid & 31;
            int row  = c >> 2;       // local b 0..7
            int o16  = c & 3;        // 16B chunk within 64B j-run
            const char* s = (const char*)(isLo ? stl : sth) + row * 64 + o16 * 16;
            float4 v = *(const float4*)s;
            unsigned short* dstb = isLo ? hbl : hbh;
            char* d = (char*)(dstb + par * 32768 + (size_t)(bg0 + row) * 512 + j0) + o16 * 16;
            *(float4*)d = v;
        }
        __syncthreads();   // STGs issued before arrive

        // ---- split-half barrier: arrive own half, wait-and-reload halves ----
        unsigned tgt = 8u * (unsigned)(t + 1);
        if (tid == 0) {
            atom_add_release(cown, 1u);
            while (ld_acquire(cnt0) < tgt) { }
        }
        __syncthreads();

        // phase-1 reload: k 0..255 (bytes 0..511)
        if (t + 1 < T_) {
            const unsigned short* srcb = rl_lo ? hbl : hbh;
            const char* src = (const char*)(srcb + par * 32768 + (size_t)(bg0 + rl_row) * 512);
            char* dst = smem + (rl_lo ? OFF_HL : OFF_HH) + rl_row * 1040;
            cp_async16_cg(dst + rl_seg,      src + rl_seg);
            cp_async16_cg(dst + rl_seg + 16, src + rl_seg + 16);
            cp_commit();
        }

        if (tid == 0) {
            while (ld_acquire(cnt1) < tgt) { }
        }
        __syncthreads();

        // phase-2 reload: k 256..511 (bytes 512..1023)
        if (t + 1 < T_) {
            const unsigned short* srcb = rl_lo ? hbl : hbh;
            const char* src = (const char*)(srcb + par * 32768 + (size_t)(bg0 + rl_row) * 512);
            char* dst = smem + (rl_lo ? OFF_HL : OFF_HH) + rl_row * 1040;
            cp_async16_cg(dst + 512 + rl_seg,      src + 512 + rl_seg);
            cp_async16_cg(dst + 512 + rl_seg + 16, src + 512 + rl_seg + 16);
            cp_commit();
        }
    }
}

// =========================================================================
// hidden[l][b][h] = out_l[T-1][h][b]
// =========================================================================
__global__ __launch_bounds__(256) void k_hidden(float* __restrict__ dst) {
    int idx = blockIdx.x * 256 + threadIdx.x;
    int l  = idx >> 15;
    int rem = idx & 32767;
    int bb = rem >> 9;
    int h  = rem & 511;
    const float* src = l ? g_out1 : g_out0;
    dst[idx] = src[((size_t)(T_ - 1) * H_ + h) * B_ + bb];
}

// =========================================================================
extern "C" void kernel_launch(void* const* d_in, const int* in_sizes, int n_in,
                              void* d_out, int out_size) {
    const float* x    = (const float*)d_in[0];
    const float* Wih0 = (const float*)d_in[1];
    const float* Whh0 = (const float*)d_in[2];
    const float* bih0 = (const float*)d_in[3];
    const float* bhh0 = (const float*)d_in[4];
    const float* Wih1 = (const float*)d_in[5];
    const float* Whh1 = (const float*)d_in[6];
    const float* bih1 = (const float*)d_in[7];
    const float* bhh1 = (const float*)d_in[8];
    const float* fcw  = (const float*)d_in[9];
    const float* fcb  = (const float*)d_in[10];
    float* out = (float*)d_out;

    (void)in_sizes; (void)n_in; (void)out_size;

    cudaFuncSetAttribute(k_gru13, cudaFuncAttributeMaxDynamicSharedMemorySize,
                         GRU13_SMEM_BYTES);
    cudaFuncSetAttribute(k_gemm_mma, cudaFuncAttributeMaxDynamicSharedMemorySize,
                         TC_SMEM_TOTAL);

    float *p_gates, *p_out0, *p_out1;
    cudaGetSymbolAddress((void**)&p_gates, g_gates);
    cudaGetSymbolAddress((void**)&p_out0,  g_out0);
    cudaGetSymbolAddress((void**)&p_out1,  g_out1);
    unsigned short *hbh, *hbl;
    cudaGetSymbolAddress((void**)&hbh, g_hbh);
    cudaGetSymbolAddress((void**)&hbl, g_hbl);
    __nv_bfloat16 *w0h, *w0l, *w1h, *w1l, *wfh, *wfl, *x0h, *x0l, *x1h, *x1l;
    cudaGetSymbolAddress((void**)&w0h, g_w0h);
    cudaGetSymbolAddress((void**)&w0l, g_w0l);
    cudaGetSymbolAddress((void**)&w1h, g_w1h);
    cudaGetSymbolAddress((void**)&w1l, g_w1l);
    cudaGetSymbolAddress((void**)&wfh, g_wfh);
    cudaGetSymbolAddress((void**)&wfl, g_wfl);
    cudaGetSymbolAddress((void**)&x0h, g_x0h);
    cudaGetSymbolAddress((void**)&x0l, g_x0l);
    cudaGetSymbolAddress((void**)&x1h, g_x1h);
    cudaGetSymbolAddress((void**)&x1l, g_x1l);

    // operand prep
    k_prep_w<<<dim3(12, 4), 256>>>(Wih0, w0h, w0l, I_);
    k_prep_w<<<dim3(12, 8), 256>>>(Wih1, w1h, w1l, H_);
    k_prep_w<<<dim3(2, 8),  256>>>(fcw,  wfh, wfl, H_);
    k_prep_x<<<dim3(1024, 4), 256>>>(x);

    // layer 0
    k_gemm_mma<<<dim3(12, 512), 256, TC_SMEM_TOTAL>>>(w0h, w0l, x0h, x0l, bih0, p_gates, 4, G_, 0);
    k_zero<<<1, 256>>>();
    k_gru13<<<128, 256, GRU13_SMEM_BYTES>>>(p_gates, Whh0, bhh0, p_out0, hbh, hbl);

    // layer 1
    k_prep_h<<<dim3(1024, 8), 256>>>(p_out0, x1h, x1l);
    k_gemm_mma<<<dim3(12, 512), 256, TC_SMEM_TOTAL>>>(w1h, w1l, x1h, x1l, bih1, p_gates, 8, G_, 0);
    k_zero<<<1, 256>>>();
    k_gru13<<<128, 256, GRU13_SMEM_BYTES>>>(p_gates, Whh1, bhh1, p_out1, hbh, hbl);

    // FC
    k_prep_h<<<dim3(1024, 8), 256>>>(p_out1, x1h, x1l);
    k_gemm_mma<<<dim3(2, 512), 256, TC_SMEM_TOTAL>>>(wfh, wfl, x1h, x1l, fcb, out, 8, O_, 1);

    k_hidden<<<256, 256>>>(out + (size_t)B_ * T_ * O_);
}

// round 17
// speedup vs baseline: 1.2851x; 1.0702x over previous
#include <cuda_runtime.h>
#include <cuda_bf16.h>
#include <cstdint>

#define B_ 64
#define T_ 1024
#define I_ 256
#define H_ 512
#define O_ 256
#define G_ 1536   // 3*H

// ======================= scratch (device globals) =======================
__device__ float g_gates[(size_t)T_ * G_ * B_];   // [t][g][b]
__device__ float g_out0[(size_t)T_ * H_ * B_];    // [t][h][b]
__device__ float g_out1[(size_t)T_ * H_ * B_];    // [t][h][b]
__device__ unsigned g_cnt[8 * 32];                 // per-group split counters (monotonic)
__device__ unsigned short g_hbh[2 * 64 * 512];     // h bf16-hi, parity double buffer, [b][k]
__device__ unsigned short g_hbl[2 * 64 * 512];     // h bf16-lo

// pre-swizzled bf16 operand tiles (GEMM phase)
__device__ __nv_bfloat16 g_w0h[12 * 4 * 8192], g_w0l[12 * 4 * 8192];
__device__ __nv_bfloat16 g_w1h[12 * 8 * 8192], g_w1l[12 * 8 * 8192];
__device__ __nv_bfloat16 g_wfh[ 2 * 8 * 8192], g_wfl[ 2 * 8 * 8192];
__device__ __nv_bfloat16 g_x0h[(size_t)T_ * 4 * 4096], g_x0l[(size_t)T_ * 4 * 4096];
__device__ __nv_bfloat16 g_x1h[(size_t)T_ * 8 * 4096], g_x1l[(size_t)T_ * 8 * 4096];

// ======================= small helpers =======================
__device__ __forceinline__ void cp_async16(void* smem_dst, const void* gsrc) {
    unsigned s = (unsigned)__cvta_generic_to_shared(smem_dst);
    asm volatile("cp.async.ca.shared.global [%0], [%1], 16;" :: "r"(s), "l"(gsrc));
}
// L2-path (no L1 allocate) — required for cross-SM-produced data
__device__ __forceinline__ void cp_async16_cg(void* smem_dst, const void* gsrc) {
    unsigned s = (unsigned)__cvta_generic_to_shared(smem_dst);
    asm volatile("cp.async.cg.shared.global [%0], [%1], 16;" :: "r"(s), "l"(gsrc));
}
__device__ __forceinline__ void cp_commit() {
    asm volatile("cp.async.commit_group;");
}
template <int N>
__device__ __forceinline__ void cp_wait() {
    asm volatile("cp.async.wait_group %0;" :: "n"(N));
}
__device__ __forceinline__ unsigned atom_add_release(unsigned* p, unsigned v) {
    unsigned old;
    asm volatile("atom.add.release.gpu.global.u32 %0, [%1], %2;"
                 : "=r"(old) : "l"(p), "r"(v) : "memory");
    return old;
}
__device__ __forceinline__ unsigned ld_acquire(const unsigned* p) {
    unsigned v;
    asm volatile("ld.acquire.gpu.global.u32 %0, [%1];" : "=r"(v) : "l"(p) : "memory");
    return v;
}
__device__ __forceinline__ uint32_t smem_u32(const void* p) {
    return (uint32_t)__cvta_generic_to_shared(p);
}
__host__ __device__ __forceinline__ uint32_t swz128(uint32_t o) {
    return o ^ ((o >> 3) & 0x70);
}
__device__ __forceinline__ unsigned short bf16hi_bits(float v, float& rem) {
    __nv_bfloat16 b = __float2bfloat16(v);
    rem = v - __bfloat162float(b);
    return *reinterpret_cast<unsigned short*>(&b);
}
__device__ __forceinline__ unsigned short bf16_bits(float v) {
    __nv_bfloat16 b = __float2bfloat16(v);
    return *reinterpret_cast<unsigned short*>(&b);
}
// fast activations: ex2.approx + rcp.approx (~1e-6 rel err)
__device__ __forceinline__ float fast_sigmoid(float x) {
    float e, r;
    asm("ex2.approx.f32 %0, %1;" : "=f"(e) : "f"(-1.4426950408889634f * x));
    asm("rcp.approx.f32 %0, %1;" : "=f"(r) : "f"(1.f + e));
    return r;
}
__device__ __forceinline__ float fast_tanh(float x) {
    float e, r;
    asm("ex2.approx.f32 %0, %1;" : "=f"(e) : "f"(2.8853900817779268f * x));
    asm("rcp.approx.f32 %0, %1;" : "=f"(r) : "f"(1.f + e));
    return 1.f - 2.f * r;   // (e-1)/(e+1)
}

// ---- mma.sync / ldmatrix (base-target PTX) ----
__device__ __forceinline__ void ldsm_x4(unsigned* r, uint32_t addr) {
    asm volatile("ldmatrix.sync.aligned.m8n8.x4.shared.b16 {%0,%1,%2,%3}, [%4];"
        : "=r"(r[0]), "=r"(r[1]), "=r"(r[2]), "=r"(r[3]) : "r"(addr));
}
__device__ __forceinline__ void ldsm_x2(unsigned* r, uint32_t addr) {
    asm volatile("ldmatrix.sync.aligned.m8n8.x2.shared.b16 {%0,%1}, [%2];"
        : "=r"(r[0]), "=r"(r[1]) : "r"(addr));
}
__device__ __forceinline__ void mma_bf16(float* d, const unsigned* a, const unsigned* b) {
    asm volatile(
        "mma.sync.aligned.m16n8k16.row.col.f32.bf16.bf16.f32 "
        "{%0,%1,%2,%3}, {%4,%5,%6,%7}, {%8,%9}, {%0,%1,%2,%3};"
        : "+f"(d[0]), "+f"(d[1]), "+f"(d[2]), "+f"(d[3])
        : "r"(a[0]), "r"(a[1]), "r"(a[2]), "r"(a[3]), "r"(b[0]), "r"(b[1]));
}

// =========================================================================
// Zero the barrier counters (before each recurrent launch; graph-safe)
// =========================================================================
__global__ void k_zero() {
    g_cnt[threadIdx.x] = 0u;
}

// =========================================================================
// Prep: W [M,K] fp32 -> hi/lo bf16 SW128 tiles [mi][s][128x64]
// =========================================================================
__global__ __launch_bounds__(256) void k_prep_w(
    const float* __restrict__ src, __nv_bfloat16* __restrict__ dh,
    __nv_bfloat16* __restrict__ dl, int K)
{
    int mi = blockIdx.x, s = blockIdx.y, nS = gridDim.y;
    size_t tbase = ((size_t)mi * nS + s) * 16384;
#pragma unroll
    for (int i = 0; i < 8; i++) {
        int it  = threadIdx.x + i * 256;
        int row = it >> 4;
        int q   = it & 15;
        float4 v = *(const float4*)(src + (size_t)(mi * 128 + row) * K + s * 64 + q * 4);
        float r0, r1, r2, r3;
        ushort4 hi, lo;
        hi.x = bf16hi_bits(v.x, r0); hi.y = bf16hi_bits(v.y, r1);
        hi.z = bf16hi_bits(v.z, r2); hi.w = bf16hi_bits(v.w, r3);
        lo.x = bf16_bits(r0); lo.y = bf16_bits(r1);
        lo.z = bf16_bits(r2); lo.w = bf16_bits(r3);
        uint32_t sw = swz128((uint32_t)(row * 128 + q * 8));
        *(ushort4*)((char*)dh + tbase + sw) = hi;
        *(ushort4*)((char*)dl + tbase + sw) = lo;
    }
}

// =========================================================================
// Prep: x[b][t][k] fp32 -> hi/lo bf16 SW128 tiles [t][s][64(b)x64(k)]
// =========================================================================
__global__ __launch_bounds__(256) void k_prep_x(const float* __restrict__ x) {
    int t = blockIdx.x, s = blockIdx.y, nS = gridDim.y;
    size_t tbase = ((size_t)t * nS + s) * 8192;
#pragma unroll
    for (int i = 0; i < 4; i++) {
        int it = threadIdx.x + i * 256;
        int b  = it >> 4;
        int q  = it & 15;
        float4 v = *(const float4*)(x + ((size_t)b * T_ + t) * I_ + s * 64 + q * 4);
        float r0, r1, r2, r3;
        ushort4 hi, lo;
        hi.x = bf16hi_bits(v.x, r0); hi.y = bf16hi_bits(v.y, r1);
        hi.z = bf16hi_bits(v.z, r2); hi.w = bf16hi_bits(v.w, r3);
        lo.x = bf16_bits(r0); lo.y = bf16_bits(r1);
        lo.z = bf16_bits(r2); lo.w = bf16_bits(r3);
        uint32_t sw = swz128((uint32_t)(b * 128 + q * 8));
        *(ushort4*)((char*)g_x0h + tbase + sw) = hi;
        *(ushort4*)((char*)g_x0l + tbase + sw) = lo;
    }
}

// =========================================================================
// Prep: out[t][h][b] fp32 -> hi/lo bf16 SW128 tiles [t][s][64(b)x64(k)]
// =========================================================================
__global__ __launch_bounds__(256) void k_prep_h(
    const float* __restrict__ src, __nv_bfloat16* __restrict__ dh,
    __nv_bfloat16* __restrict__ dl)
{
    __shared__ float sm[64 * 65];
    int t = blockIdx.x, s = blockIdx.y, nS = gridDim.y;
    size_t tbase = ((size_t)t * nS + s) * 8192;
    const float* blk = src + ((size_t)t * H_ + s * 64) * B_;
#pragma unroll
    for (int i = 0; i < 16; i++) {
        int idx = threadIdx.x + i * 256;
        int k = idx >> 6, b = idx & 63;
        sm[k * 65 + b] = blk[idx];
    }
    __syncthreads();
#pragma unroll
    for (int i = 0; i < 4; i++) {
        int it = threadIdx.x + i * 256;
        int b  = it >> 4;
        int q  = it & 15;
        float v0 = sm[(q * 4 + 0) * 65 + b];
        float v1 = sm[(q * 4 + 1) * 65 + b];
        float v2 = sm[(q * 4 + 2) * 65 + b];
        float v3 = sm[(q * 4 + 3) * 65 + b];
        float r0, r1, r2, r3;
        ushort4 hi, lo;
        hi.x = bf16hi_bits(v0, r0); hi.y = bf16hi_bits(v1, r1);
        hi.z = bf16hi_bits(v2, r2); hi.w = bf16hi_bits(v3, r3);
        lo.x = bf16_bits(r0); lo.y = bf16_bits(r1);
        lo.z = bf16_bits(r2); lo.w = bf16_bits(r3);
        uint32_t sw = swz128((uint32_t)(b * 128 + q * 8));
        *(ushort4*)((char*)dh + tbase + sw) = hi;
        *(ushort4*)((char*)dl + tbase + sw) = lo;
    }
}

// =========================================================================
// mma.sync GEMM (proven version: M=128 tiles)
// =========================================================================
#define TCB_BYTES 65536
#define TC_SMEM_TOTAL (1024 + 2 * TCB_BYTES)

__global__ __launch_bounds__(256) void k_gemm_mma(
    const __nv_bfloat16* __restrict__ Wh, const __nv_bfloat16* __restrict__ Wl,
    const __nv_bfloat16* __restrict__ Xh, const __nv_bfloat16* __restrict__ Xl,
    const float* __restrict__ bias, float* __restrict__ C,
    int nS, int M, int mode)
{
    extern __shared__ __align__(16) char smem[];
    uint32_t sb = smem_u32(smem);
    int tid  = threadIdx.x;
    int wid  = tid >> 5;
    int lane = tid & 31;
    int mi   = blockIdx.x;
    int m0   = mi * 128;
    int t0   = blockIdx.y * 2;

    int wm = (wid >> 1) * 32;
    int wn = (wid & 1);

    uint32_t pA = (uint32_t)((wm + (lane & 15)) * 128 + (lane >> 4) * 16);
    uint32_t rowB = (uint32_t)((lane & 7) + ((lane >> 4) & 1) * 8);
    uint32_t koffB = (uint32_t)(((lane >> 3) & 1) * 16);

    float acc[2][8][4];
#pragma unroll
    for (int i = 0; i < 2; i++)
#pragma unroll
        for (int n = 0; n < 8; n++)
#pragma unroll
            for (int c = 0; c < 4; c++) acc[i][n][c] = 0.f;

    auto issue_slab = [&](int s, int bi) {
        char* dst = smem + 1024 + bi * TCB_BYTES;
        const char* wh  = (const char*)Wh + ((size_t)mi * nS + s) * 16384;
        const char* wl  = (const char*)Wl + ((size_t)mi * nS + s) * 16384;
        const char* x0h = (const char*)Xh + ((size_t)t0 * nS + s) * 8192;
        const char* x1h = (const char*)Xh + ((size_t)(t0 + 1) * nS + s) * 8192;
        const char* x0l = (const char*)Xl + ((size_t)t0 * nS + s) * 8192;
        const char* x1l = (const char*)Xl + ((size_t)(t0 + 1) * nS + s) * 8192;
#pragma unroll
        for (int i = 0; i < 16; i++) {
            int c   = tid + i * 256;
            int reg = c >> 10;
            int off = (c & 1023) * 16;
            const char* src;
            if      (reg == 0) src = wh + off;
            else if (reg == 1) src = wl + off;
            else if (reg == 2) src = (off < 8192) ? x0h + off : x1h + (off - 8192);
            else               src = (off < 8192) ? x0l + off : x1l + (off - 8192);
            cp_async16(dst + reg * 16384 + off, src);
        }
        cp_commit();
    };

    issue_slab(0, 0);

    for (int s = 0; s < nS; s++) {
        int bi = s & 1;
        if (s + 1 < nS) {
            issue_slab(s + 1, (s + 1) & 1);
            cp_wait<1>();
        } else {
            cp_wait<0>();
        }
        __syncthreads();

        uint32_t bufb = sb + 1024 + (uint32_t)bi * TCB_BYTES;
        uint32_t aH = bufb;
        uint32_t aL = bufb + 16384;
        uint32_t bH = bufb + 32768 + (uint32_t)wn * 8192;
        uint32_t bL = bufb + 49152 + (uint32_t)wn * 8192;

#pragma unroll
        for (int ks = 0; ks < 4; ks++) {
            unsigned ah[2][4], al[2][4];
            ldsm_x4(ah[0], aH + swz128(pA + ks * 32));
            ldsm_x4(ah[1], aH + swz128(pA + 2048 + ks * 32));
            ldsm_x4(al[0], aL + swz128(pA + ks * 32));
            ldsm_x4(al[1], aL + swz128(pA + 2048 + ks * 32));
#pragma unroll
            for (int half = 0; half < 2; half++) {
                unsigned bh2[2][4], bl2[2][4];
#pragma unroll
                for (int np2 = 0; np2 < 2; np2++) {
                    int np = half * 2 + np2;
                    uint32_t pB = (uint32_t)((np * 16 + rowB) * 128) + koffB;
                    ldsm_x4(bh2[np2], bH + swz128(pB + ks * 32));
                    ldsm_x4(bl2[np2], bL + swz128(pB + ks * 32));
                }
#pragma unroll
                for (int np2 = 0; np2 < 2; np2++) {
#pragma unroll
                    for (int e = 0; e < 2; e++) {
                        int nt = half * 4 + np2 * 2 + e;
                        const unsigned* bfh = &bh2[np2][e * 2];
                        const unsigned* bfl = &bl2[np2][e * 2];
#pragma unroll
                        for (int i = 0; i < 2; i++) {
                            mma_bf16(acc[i][nt], ah[i], bfh);
                            mma_bf16(acc[i][nt], ah[i], bfl);
                            mma_bf16(acc[i][nt], al[i], bfh);
                        }
                    }
                }
            }
        }
        __syncthreads();
    }

    int qrow = lane >> 2;
    int qcol = (lane & 3) * 2;

    if (mode == 0) {
        int t = t0 + wn;
#pragma unroll
        for (int i = 0; i < 2; i++) {
            int r0 = wm + i * 16 + qrow;
            int r1 = r0 + 8;
            float bb0 = bias[m0 + r0];
            float bb1 = bias[m0 + r1];
            float* d0 = C + ((size_t)t * M + m0 + r0) * B_;
            float* d1 = C + ((size_t)t * M + m0 + r1) * B_;
#pragma unroll
            for (int nt = 0; nt < 8; nt++) {
                int col = nt * 8 + qcol;
                *(float2*)(d0 + col) = make_float2(acc[i][nt][0] + bb0, acc[i][nt][1] + bb0);
                *(float2*)(d1 + col) = make_float2(acc[i][nt][2] + bb1, acc[i][nt][3] + bb1);
            }
        }
    } else {
        float* stage = (float*)(smem + 1024);
#pragma unroll
        for (int i = 0; i < 2; i++) {
            int r0 = wm + i * 16 + qrow;
            int r1 = r0 + 8;
            float bb0 = bias[m0 + r0];
            float bb1 = bias[m0 + r1];
#pragma unroll
            for (int nt = 0; nt < 8; nt++) {
                int col = wn * 64 + nt * 8 + qcol;
                stage[r0 * 132 + col]     = acc[i][nt][0] + bb0;
                stage[r0 * 132 + col + 1] = acc[i][nt][1] + bb0;
                stage[r1 * 132 + col]     = acc[i][nt][2] + bb1;
                stage[r1 * 132 + col + 1] = acc[i][nt][3] + bb1;
            }
        }
        __syncthreads();
        int n    = tid >> 1;
        int half = tid & 1;
        int tt   = t0 + (n >> 6);
        int b2   = n & 63;
        float* dst = C + ((size_t)b2 * T_ + tt) * M + m0 + half * 64;
#pragma unroll
        for (int q = 0; q < 16; q++) {
            float4 v = make_float4(stage[(half * 64 + q * 4 + 0) * 132 + n],
                                   stage[(half * 64 + q * 4 + 1) * 132 + n],
                                   stage[(half * 64 + q * 4 + 2) * 132 + n],
                                   stage[(half * 64 + q * 4 + 3) * 132 + n]);
            *(float4*)(dst + q * 4) = v;
        }
    }
}

// =========================================================================
// Persistent GRU layer (R16 base) + REGISTER-RESIDENT W-hi fragments.
// 128 CTAs = 8 batch-groups (8 b) x 16 j-subs (32 j = 96 gate-rows).
// Warp w<6 preloads Ah[32][4] (its 16-row W-hi tile, all K) via ldmatrix
// ONCE; per-step smem reads drop to W-lo + h operands.
// Split-half barrier + cp.async split-K reload + fast activations.
// =========================================================================
#define OFF_WL  99840
#define OFF_HH  199680
#define OFF_HL  208000
#define OFF_HG  216640
#define OFF_STG 221248
#define GRU14_SMEM_BYTES 222272

__global__ __launch_bounds__(256) void k_gru14(
    const float* __restrict__ gates,   // [t][g][b], includes b_ih
    const float* __restrict__ Whh,     // [3H][H]
    const float* __restrict__ bhh,     // [3H]
    float* __restrict__ out,           // [t][h][b]
    unsigned short* __restrict__ hbh,  // [2][64][512] bf16-hi bits
    unsigned short* __restrict__ hbl)  // [2][64][512] bf16-lo bits
{
    extern __shared__ __align__(16) char smem[];
    uint32_t sb = smem_u32(smem);

    int tid   = threadIdx.x;
    int w     = tid >> 5;
    int lane  = tid & 31;
    int group = blockIdx.x >> 4;    // 0..7
    int sub   = blockIdx.x & 15;    // 0..15
    int jj    = tid >> 3;           // 0..31
    int bl    = tid & 7;            // 0..7
    int j0    = sub * 32;
    int bg0   = group * 8;
    int j     = j0 + jj;
    int b     = bg0 + bl;
    unsigned* cnt0 = &g_cnt[group * 32];        // subs 0-7 (k 0..255)
    unsigned* cnt1 = &g_cnt[group * 32 + 16];   // subs 8-15 (k 256..511)
    unsigned* cown = (sub < 8) ? cnt0 : cnt1;

    // ---- init: Whh slice -> bf16 hi/lo smem, row = jj*3+gate ----
    for (int idx = tid; idx < 96 * 512; idx += 256) {
        int r = idx >> 9;           // 0..95
        int k = idx & 511;
        int gg = r % 3;
        int ww = r / 3;
        float v = Whh[((size_t)(gg * H_ + j0 + ww)) * H_ + k];
        float rem;
        unsigned short hi = bf16hi_bits(v, rem);
        unsigned short lo = bf16_bits(rem);
        *(unsigned short*)(smem + r * 1040 + k * 2)          = hi;
        *(unsigned short*)(smem + OFF_WL + r * 1040 + k * 2) = lo;
    }
    // zero h smem (hh + hl)
    for (int idx = tid; idx < (2 * 8320) / 4; idx += 256)
        *(uint32_t*)(smem + OFF_HH + idx * 4) = 0u;

    float bhr = bhh[j];
    float bhz = bhh[H_ + j];
    float bhn = bhh[2 * H_ + j];
    float hold = 0.f;

    const float* gp = gates + (size_t)j * B_ + b;
    const size_t tstride = (size_t)G_ * B_;
    const size_t goff    = (size_t)H_ * B_;
    float xr = __ldcs(gp);
    float xz = __ldcs(gp + goff);
    float xn = __ldcs(gp + 2 * goff);

    // ldmatrix address patterns (byte offsets, k-chunk added in loop)
    uint32_t paH = sb + (uint32_t)((w * 16 + (lane & 15)) * 1040 + (lane >> 4) * 16);
    uint32_t paL = paH + OFF_WL;
    uint32_t pbH = sb + OFF_HH + (uint32_t)((lane & 7) * 1040 + ((lane >> 3) & 1) * 16);
    uint32_t pbL = pbH + (OFF_HL - OFF_HH);
    float* hg = (float*)(smem + OFF_HG);
    unsigned short* sth = (unsigned short*)(smem + OFF_STG);   // [8 b][32 jj]
    unsigned short* stl = sth + 256;

    // reload thread mapping: threads 0-127 -> hi, 128-255 -> lo
    int rl_lo  = tid >> 7;                 // 0 = hi, 1 = lo
    int rl_row = (tid >> 4) & 7;           // local b 0..7
    int rl_seg = (tid & 15) * 32;          // 0..480 within 512B half

    __syncthreads();

    // ---- preload W-hi fragments into registers (once) ----
    unsigned Ah[32][4];
    if (w < 6) {
#pragma unroll
        for (int c = 0; c < 32; c++)
            ldsm_x4(Ah[c], paH + (uint32_t)c * 32);
    }

    for (int t = 0; t < T_; t++) {
        int par = t & 1;

        // ---- wait first reload half, then MMA k 0..15 ----
        if (t > 0) cp_wait<1>();
        __syncthreads();

        float acc[4] = {0.f, 0.f, 0.f, 0.f};
        if (w < 6) {
#pragma unroll
            for (int ks = 0; ks < 16; ks++) {
                uint32_t ko = (uint32_t)ks * 32;
                unsigned al[4], bh2[2], bl2[2];
                ldsm_x4(al, paL + ko);
                ldsm_x2(bh2, pbH + ko);
                ldsm_x2(bl2, pbL + ko);
                mma_bf16(acc, Ah[ks], bh2);
                mma_bf16(acc, Ah[ks], bl2);
                mma_bf16(acc, al, bh2);
            }
        }

        // ---- wait second reload half, then MMA k 16..31 ----
        if (t > 0) cp_wait<0>();
        __syncthreads();

        if (w < 6) {
#pragma unroll
            for (int ks = 16; ks < 32; ks++) {
                uint32_t ko = (uint32_t)ks * 32;
                unsigned al[4], bh2[2], bl2[2];
                ldsm_x4(al, paL + ko);
                ldsm_x2(bh2, pbH + ko);
                ldsm_x2(bl2, pbL + ko);
                mma_bf16(acc, Ah[ks], bh2);
                mma_bf16(acc, Ah[ks], bl2);
                mma_bf16(acc, al, bh2);
            }
            int r0 = w * 16 + (lane >> 2);
            *(float2*)&hg[r0 * 12 + (lane & 3) * 2]       = make_float2(acc[0], acc[1]);
            *(float2*)&hg[(r0 + 8) * 12 + (lane & 3) * 2] = make_float2(acc[2], acc[3]);
        }
        __syncthreads();

        // ---- gate math (all 256 threads, one (j,b) each) ----
        float ar = hg[(jj * 3 + 0) * 12 + bl];
        float az = hg[(jj * 3 + 1) * 12 + bl];
        float an = hg[(jj * 3 + 2) * 12 + bl];

        float r = fast_sigmoid(xr + ar + bhr);
        float z = fast_sigmoid(xz + az + bhz);
        float n = fast_tanh(xn + r * (an + bhn));
        float hnew = (1.f - z) * n + z * hold;
        hold = hnew;

        out[((size_t)t * H_ + j) * B_ + b] = hnew;
        {
            float rem;
            sth[bl * 32 + jj] = bf16hi_bits(hnew, rem);
            stl[bl * 32 + jj] = bf16_bits(rem);
        }

        // prefetch next-step gates (independent of h)
        if (t + 1 < T_) {
            const float* gq = gp + (size_t)(t + 1) * tstride;
            xr = __ldcs(gq);
            xz = __ldcs(gq + goff);
            xn = __ldcs(gq + 2 * goff);
        }

        __syncthreads();   // stage ready

        // ---- coalesced h publication: 64 threads, 16B each ----
        if (tid < 64) {
            int isLo = tid >> 5;
            int c    = tid & 31;
            int row  = c >> 2;       // local b 0..7
            int o16  = c & 3;        // 16B chunk within 64B j-run
            const char* s = (const char*)(isLo ? stl : sth) + row * 64 + o16 * 16;
            float4 v = *(const float4*)s;
            unsigned short* dstb = isLo ? hbl : hbh;
            char* d = (char*)(dstb + par * 32768 + (size_t)(bg0 + row) * 512 + j0) + o16 * 16;
            *(float4*)d = v;
        }
        __syncthreads();   // STGs issued before arrive

        // ---- split-half barrier: arrive own half, wait-and-reload halves ----
        unsigned tgt = 8u * (unsigned)(t + 1);
        if (tid == 0) {
            atom_add_release(cown, 1u);
            while (ld_acquire(cnt0) < tgt) { }
        }
        __syncthreads();

        // phase-1 reload: k 0..255 (bytes 0..511)
        if (t + 1 < T_) {
            const unsigned short* srcb = rl_lo ? hbl : hbh;
            const char* src = (const char*)(srcb + par * 32768 + (size_t)(bg0 + rl_row) * 512);
            char* dst = smem + (rl_lo ? OFF_HL : OFF_HH) + rl_row * 1040;
            cp_async16_cg(dst + rl_seg,      src + rl_seg);
            cp_async16_cg(dst + rl_seg + 16, src + rl_seg + 16);
            cp_commit();
        }

        if (tid == 0) {
            while (ld_acquire(cnt1) < tgt) { }
        }
        __syncthreads();

        // phase-2 reload: k 256..511 (bytes 512..1023)
        if (t + 1 < T_) {
            const unsigned short* srcb = rl_lo ? hbl : hbh;
            const char* src = (const char*)(srcb + par * 32768 + (size_t)(bg0 + rl_row) * 512);
            char* dst = smem + (rl_lo ? OFF_HL : OFF_HH) + rl_row * 1040;
            cp_async16_cg(dst + 512 + rl_seg,      src + 512 + rl_seg);
            cp_async16_cg(dst + 512 + rl_seg + 16, src + 512 + rl_seg + 16);
            cp_commit();
        }
    }
}

// =========================================================================
// hidden[l][b][h] = out_l[T-1][h][b]
// =========================================================================
__global__ __launch_bounds__(256) void k_hidden(float* __restrict__ dst) {
    int idx = blockIdx.x * 256 + threadIdx.x;
    int l  = idx >> 15;
    int rem = idx & 32767;
    int bb = rem >> 9;
    int h  = rem & 511;
    const float* src = l ? g_out1 : g_out0;
    dst[idx] = src[((size_t)(T_ - 1) * H_ + h) * B_ + bb];
}

// =========================================================================
extern "C" void kernel_launch(void* const* d_in, const int* in_sizes, int n_in,
                              void* d_out, int out_size) {
    const float* x    = (const float*)d_in[0];
    const float* Wih0 = (const float*)d_in[1];
    const float* Whh0 = (const float*)d_in[2];
    const float* bih0 = (const float*)d_in[3];
    const float* bhh0 = (const float*)d_in[4];
    const float* Wih1 = (const float*)d_in[5];
    const float* Whh1 = (const float*)d_in[6];
    const float* bih1 = (const float*)d_in[7];
    const float* bhh1 = (const float*)d_in[8];
    const float* fcw  = (const float*)d_in[9];
    const float* fcb  = (const float*)d_in[10];
    float* out = (float*)d_out;

    (void)in_sizes; (void)n_in; (void)out_size;

    cudaFuncSetAttribute(k_gru14, cudaFuncAttributeMaxDynamicSharedMemorySize,
                         GRU14_SMEM_BYTES);
    cudaFuncSetAttribute(k_gemm_mma, cudaFuncAttributeMaxDynamicSharedMemorySize,
                         TC_SMEM_TOTAL);

    float *p_gates, *p_out0, *p_out1;
    cudaGetSymbolAddress((void**)&p_gates, g_gates);
    cudaGetSymbolAddress((void**)&p_out0,  g_out0);
    cudaGetSymbolAddress((void**)&p_out1,  g_out1);
    unsigned short *hbh, *hbl;
    cudaGetSymbolAddress((void**)&hbh, g_hbh);
    cudaGetSymbolAddress((void**)&hbl, g_hbl);
    __nv_bfloat16 *w0h, *w0l, *w1h, *w1l, *wfh, *wfl, *x0h, *x0l, *x1h, *x1l;
    cudaGetSymbolAddress((void**)&w0h, g_w0h);
    cudaGetSymbolAddress((void**)&w0l, g_w0l);
    cudaGetSymbolAddress((void**)&w1h, g_w1h);
    cudaGetSymbolAddress((void**)&w1l, g_w1l);
    cudaGetSymbolAddress((void**)&wfh, g_wfh);
    cudaGetSymbolAddress((void**)&wfl, g_wfl);
    cudaGetSymbolAddress((void**)&x0h, g_x0h);
    cudaGetSymbolAddress((void**)&x0l, g_x0l);
    cudaGetSymbolAddress((void**)&x1h, g_x1h);
    cudaGetSymbolAddress((void**)&x1l, g_x1l);

    // operand prep
    k_prep_w<<<dim3(12, 4), 256>>>(Wih0, w0h, w0l, I_);
    k_prep_w<<<dim3(12, 8), 256>>>(Wih1, w1h, w1l, H_);
    k_prep_w<<<dim3(2, 8),  256>>>(fcw,  wfh, wfl, H_);
    k_prep_x<<<dim3(1024, 4), 256>>>(x);

    // layer 0
    k_gemm_mma<<<dim3(12, 512), 256, TC_SMEM_TOTAL>>>(w0h, w0l, x0h, x0l, bih0, p_gates, 4, G_, 0);
    k_zero<<<1, 256>>>();
    k_gru14<<<128, 256, GRU14_SMEM_BYTES>>>(p_gates, Whh0, bhh0, p_out0, hbh, hbl);

    // layer 1
    k_prep_h<<<dim3(1024, 8), 256>>>(p_out0, x1h, x1l);
    k_gemm_mma<<<dim3(12, 512), 256, TC_SMEM_TOTAL>>>(w1h, w1l, x1h, x1l, bih1, p_gates, 8, G_, 0);
    k_zero<<<1, 256>>>();
    k_gru14<<<128, 256, GRU14_SMEM_BYTES>>>(p_gates, Whh1, bhh1, p_out1, hbh, hbl);

    // FC
    k_prep_h<<<dim3(1024, 8), 256>>>(p_out1, x1h, x1l);
    k_gemm_mma<<<dim3(2, 512), 256, TC_SMEM_TOTAL>>>(wfh, wfl, x1h, x1l, fcb, out, 8, O_, 1);

    k_hidden<<<256, 256>>>(out + (size_t)B_ * T_ * O_);
}